// round 14
// baseline (speedup 1.0000x reference)
#include <cuda_runtime.h>
#include <cuda_fp16.h>
#include <math.h>

#define Bn   2
#define Cn   128
#define Hs   56
#define Nn   3136
#define NHn  4
#define HFn  341
#define TOK  (Bn*Nn)
#define LDF  352

// fp32 scratch
__device__ __align__(256) float g_x2 [TOK*Cn];
__device__ __align__(256) float g_b512[512];
// half scratch
__device__ __align__(256) __half g_t1h[TOK*512];
__device__ __align__(256) __half g_qsh[8*Nn*32];
__device__ __align__(256) __half g_qnh[8*Nn*32];
__device__ __align__(256) __half g_klh[8*Nn*32];
__device__ __align__(256) __half g_vlh[8*Nn*32];
__device__ __align__(256) __half g_f1h[TOK*682];
__device__ __align__(256) __half g_yh [TOK*Cn];
__device__ __align__(256) __half g_xph[TOK*Cn];
__device__ __align__(256) __half g_atth[TOK*Cn];
__device__ __align__(256) __half g_y2h[TOK*Cn];
__device__ __align__(256) __half g_kph[TOK*Cn];
__device__ __align__(256) __half g_vph[TOK*Cn];
__device__ __align__(256) __half g_gbh[TOK*LDF];
// converted weights pool (hi only)
#define OQ   0
#define OKV  16384
#define OSR  49152
#define OPJ  65536
#define OF1  81920
#define OF2  169216
#define WTOT 214272
__device__ __align__(256) __half g_wh[WTOT];

__device__ __forceinline__ float gelu_exact(float x) {
    return 0.5f * x * (1.0f + erff(x * 0.70710678118654752f));
}
__device__ __forceinline__ unsigned h2pack(float a, float b) {
    __half2 h = __floats2half2_rn(a, b);
    return *(unsigned*)&h;
}
__device__ __forceinline__ void mma16816(float* c, const unsigned* a, unsigned b0, unsigned b1) {
    asm volatile("mma.sync.aligned.m16n8k16.row.col.f32.f16.f16.f32 "
        "{%0,%1,%2,%3}, {%4,%5,%6,%7}, {%8,%9}, {%0,%1,%2,%3};"
        : "+f"(c[0]), "+f"(c[1]), "+f"(c[2]), "+f"(c[3])
        : "r"(a[0]), "r"(a[1]), "r"(a[2]), "r"(a[3]), "r"(b0), "r"(b1));
}

// ---------- single-launch weight conversion (hi only) + fused bias ----------
__global__ void cvt_all(const float* __restrict__ q_w, const float* __restrict__ kv_w,
                        const float* __restrict__ sr_w, const float* __restrict__ proj_w,
                        const float* __restrict__ fc1_w, const float* __restrict__ fc2_w,
                        const float* __restrict__ q_b, const float* __restrict__ kv_b,
                        const float* __restrict__ sr_b,
                        __half* __restrict__ wh, float* __restrict__ b512)
{
    int i = blockIdx.x * 256 + threadIdx.x;
    if (i < WTOT) {
        float v;
        if      (i < OKV) v = q_w[i];
        else if (i < OSR) v = kv_w[i - OKV];
        else if (i < OPJ) v = sr_w[i - OSR];
        else if (i < OF1) v = proj_w[i - OPJ];
        else if (i < OF2) v = fc1_w[i - OF1];
        else {
            int j = i - OF2, r = j / LDF, c = j - r * LDF;
            v = (c < HFn) ? fc2_w[r * HFn + c] : 0.f;
        }
        wh[i] = __float2half_rn(v);
    } else if (i < WTOT + 512) {
        int j = i - WTOT;
        b512[j] = (j < 128) ? q_b[j] : (j < 384) ? kv_b[j - 128] : sr_b[j - 384];
    }
}

// ---------- LayerNorm (channel-major in) -> fp16 token-major ----------
__global__ void ln_kernel(const float* __restrict__ in, const float* __restrict__ w,
                          const float* __restrict__ bvec, __half* __restrict__ oh)
{
    int warp = blockIdx.x * 8 + (threadIdx.x >> 5);
    int lane = threadIdx.x & 31;
    int bb = warp / Nn, n = warp - bb * Nn;
    const float* p = in + (size_t)bb * (Cn*Nn) + n;
    float v[4], s = 0.f, s2 = 0.f;
#pragma unroll
    for (int pp = 0; pp < 2; pp++) {
        int c0 = 2*lane + 64*pp;
        v[2*pp]   = p[(size_t)c0 * Nn];
        v[2*pp+1] = p[(size_t)(c0+1) * Nn];
        s += v[2*pp] + v[2*pp+1];
        s2 += v[2*pp]*v[2*pp] + v[2*pp+1]*v[2*pp+1];
    }
#pragma unroll
    for (int d = 1; d < 32; d <<= 1) {
        s  += __shfl_xor_sync(0xffffffffu, s,  d);
        s2 += __shfl_xor_sync(0xffffffffu, s2, d);
    }
    float mu = s * (1.0f/128.0f);
    float rstd = rsqrtf(s2*(1.0f/128.0f) - mu*mu + 1e-5f);
    unsigned* ohp = (unsigned*)oh;
#pragma unroll
    for (int pp = 0; pp < 2; pp++) {
        int c0 = 2*lane + 64*pp;
        float a = (v[2*pp]  -mu)*rstd*w[c0]   + bvec[c0];
        float b = (v[2*pp+1]-mu)*rstd*w[c0+1] + bvec[c0+1];
        ohp[warp*64 + lane + 32*pp] = h2pack(a, b);
    }
}

// ---------- HMMA GEMM: single fp16 A x W ----------
// mode 0: fp32 out; 1: fp32 +res; 2: transposed channel-major +res; 3: fp16 out
__global__ void __launch_bounds__(128) hgemm2(
    const __half* __restrict__ Ah, const __half* __restrict__ Wh, int ld,
    const float* __restrict__ bias, float* __restrict__ out,
    int ldo, int Nout, int mode, const float* __restrict__ res)
{
    const int m0 = blockIdx.y * 64;
    const int n0 = blockIdx.x * 64;
    const int warp = threadIdx.x >> 5;
    const int lane = threadIdx.x & 31;
    const int r  = lane >> 2;
    const int c2 = (lane & 3) * 2;

    float acc[8][4];
#pragma unroll
    for (int t = 0; t < 8; t++)
#pragma unroll
        for (int i = 0; i < 4; i++) acc[t][i] = 0.f;

    const int row1 = m0 + warp*16 + r;
    const __half* a1h = Ah + (size_t)row1 * ld;
    const __half* a2h = a1h + (size_t)8 * ld;

    const int nr = n0 + (lane >> 2);
    const __half* wrow[8];
#pragma unroll
    for (int nt = 0; nt < 8; nt++) {
        int n = nr + nt*8;
        int nc = (n < Nout) ? n : (Nout - 1);
        wrow[nt] = Wh + (size_t)nc * ld;
    }

    const int KC = ld / 32;
    for (int kc = 0; kc < KC; kc++) {
#pragma unroll
        for (int ks = 0; ks < 2; ks++) {
            int d0 = kc*32 + ks*16 + c2;
            unsigned ah[4];
            ah[0] = *(const unsigned*)&a1h[d0];
            ah[1] = *(const unsigned*)&a2h[d0];
            ah[2] = *(const unsigned*)&a1h[d0+8];
            ah[3] = *(const unsigned*)&a2h[d0+8];
#pragma unroll
            for (int nt = 0; nt < 8; nt++) {
                unsigned bh0 = *(const unsigned*)&wrow[nt][d0];
                unsigned bh1 = *(const unsigned*)&wrow[nt][d0+8];
                mma16816(acc[nt], ah, bh0, bh1);
            }
        }
    }

    int m1 = row1, m2 = row1 + 8;
#pragma unroll
    for (int nt = 0; nt < 8; nt++) {
        int n = n0 + nt*8 + c2;
#pragma unroll
        for (int j = 0; j < 2; j++) {
            int nn = n + j;
            if (nn >= Nout) continue;
            float v1 = acc[nt][j]   + bias[nn];
            float v2 = acc[nt][2+j] + bias[nn];
            if (mode == 0) {
                out[(size_t)m1*ldo + nn] = v1;
                out[(size_t)m2*ldo + nn] = v2;
            } else if (mode == 1) {
                size_t i1 = (size_t)m1*ldo + nn, i2 = (size_t)m2*ldo + nn;
                out[i1] = v1 + res[i1];
                out[i2] = v2 + res[i2];
            } else if (mode == 2) {
                int b1 = m1 / Nn, t1i = m1 - b1*Nn;
                int b2 = m2 / Nn, t2i = m2 - b2*Nn;
                size_t i1 = ((size_t)b1*Cn + nn)*Nn + t1i;
                size_t i2 = ((size_t)b2*Cn + nn)*Nn + t2i;
                out[i1] = v1 + res[i1];
                out[i2] = v2 + res[i2];
            } else {
                __half* oh = (__half*)out;
                oh[(size_t)m1*ldo + nn] = __float2half_rn(v1);
                oh[(size_t)m2*ldo + nn] = __float2half_rn(v2);
            }
        }
    }
}

// ---------- HMMA kv GEMM with fused l2norm/split epilogue -> kph/vph fp16 ----------
__global__ void __launch_bounds__(128) hgemm_kv(
    const __half* __restrict__ Ah, const __half* __restrict__ Wh,
    const float* __restrict__ bias,
    __half* __restrict__ kph, __half* __restrict__ vph)
{
    const int m0 = blockIdx.y * 64;
    const int n0 = blockIdx.x * 64;
    const int warp = threadIdx.x >> 5;
    const int lane = threadIdx.x & 31;
    const int r  = lane >> 2;
    const int c2 = (lane & 3) * 2;
    const int ld = 128;

    float acc[8][4];
#pragma unroll
    for (int t = 0; t < 8; t++)
#pragma unroll
        for (int i = 0; i < 4; i++) acc[t][i] = 0.f;

    const int row1 = m0 + warp*16 + r;
    const __half* a1h = Ah + (size_t)row1 * ld;
    const __half* a2h = a1h + (size_t)8 * ld;

    const int nr = n0 + (lane >> 2);
    const __half* wrow[8];
#pragma unroll
    for (int nt = 0; nt < 8; nt++)
        wrow[nt] = Wh + (size_t)(nr + nt*8) * ld;

#pragma unroll
    for (int kc = 0; kc < 4; kc++) {
#pragma unroll
        for (int ks = 0; ks < 2; ks++) {
            int d0 = kc*32 + ks*16 + c2;
            unsigned ah[4];
            ah[0] = *(const unsigned*)&a1h[d0];
            ah[1] = *(const unsigned*)&a2h[d0];
            ah[2] = *(const unsigned*)&a1h[d0+8];
            ah[3] = *(const unsigned*)&a2h[d0+8];
#pragma unroll
            for (int nt = 0; nt < 8; nt++) {
                unsigned bh0 = *(const unsigned*)&wrow[nt][d0];
                unsigned bh1 = *(const unsigned*)&wrow[nt][d0+8];
                mma16816(acc[nt], ah, bh0, bh1);
            }
        }
    }

#pragma unroll
    for (int half = 0; half < 2; half++) {
        int m = row1 + half*8;
        int bb = m / Nn, n = m - bb*Nn;
        float vals[16];
#pragma unroll
        for (int nt = 0; nt < 8; nt++)
#pragma unroll
            for (int j = 0; j < 2; j++)
                vals[nt*2+j] = acc[nt][half*2+j] + bias[n0 + nt*8 + c2 + j];
        if (n0 < 128) {
            float se = 0.f, so = 0.f;
#pragma unroll
            for (int i = 0; i < 8; i++) { se += vals[i]*vals[i]; so += vals[8+i]*vals[8+i]; }
            se += __shfl_xor_sync(0xffffffffu, se, 1);
            se += __shfl_xor_sync(0xffffffffu, se, 2);
            so += __shfl_xor_sync(0xffffffffu, so, 1);
            so += __shfl_xor_sync(0xffffffffu, so, 2);
            float ke = 1.0f / fmaxf(sqrtf(se), 1e-12f);
            float ko = 1.0f / fmaxf(sqrtf(so), 1e-12f);
#pragma unroll
            for (int nt = 0; nt < 8; nt++) {
                int col = n0 + nt*8 + c2;
                int head = col >> 5;
                float sc = (nt < 4) ? ke : ko;
                __half2 hv = __floats2half2_rn(vals[nt*2]*sc, vals[nt*2+1]*sc);
                *(__half2*)&kph[((size_t)(bb*NHn + head)*Nn + n)*32 + (col & 31)] = hv;
            }
        } else {
#pragma unroll
            for (int nt = 0; nt < 8; nt++) {
                int col = n0 - 128 + nt*8 + c2;
                int head = col >> 5;
                __half2 hv = __floats2half2_rn(vals[nt*2], vals[nt*2+1]);
                *(__half2*)&vph[((size_t)(bb*NHn + head)*Nn + n)*32 + (col & 31)] = hv;
            }
        }
    }
}

// ---------- pointwise after fused QKVSR GEMM (fp16 in, fp16 out) ----------
__global__ void pointwise1(const __half* __restrict__ t1h, const float* __restrict__ temp,
                           const float* __restrict__ qe, const float* __restrict__ plnw,
                           const float* __restrict__ plnb,
                           __half* __restrict__ qsh, __half* __restrict__ qnh,
                           __half* __restrict__ klh, __half* __restrict__ vlh,
                           __half* __restrict__ xph)
{
    int t = blockIdx.x * 8 + (threadIdx.x >> 5);
    int lane = threadIdx.x & 31;
    int bb = t / Nn, n = t - bb * Nn;
    int h = lane >> 3;
    int g = bb * NHn + h;
    const __half2* row = (const __half2*)(t1h + (size_t)t * 512);
    unsigned base = ((unsigned)g*Nn + n)*16 + (lane & 7)*2;

    __half2 qa = row[2*lane], qb = row[2*lane + 1];
    float q0 = __half2float(qa.x), q1 = __half2float(qa.y);
    float q2 = __half2float(qb.x), q3 = __half2float(qb.y);
    float ss = q0*q0 + q1*q1 + q2*q2 + q3*q3;
    ss += __shfl_xor_sync(0xffffffffu, ss, 1);
    ss += __shfl_xor_sync(0xffffffffu, ss, 2);
    ss += __shfl_xor_sync(0xffffffffu, ss, 4);
    float inv = 1.0f / fmaxf(sqrtf(ss), 1e-12f);
    float n0 = q0*inv, n1 = q1*inv, n2 = q2*inv, n3 = q3*inv;
    float tv = temp[h];
    float sp = log1pf(__expf(tv));
    float4 qe4 = ((const float4*)qe)[h*8 + (lane & 7)];
    ((unsigned*)qnh)[base]   = h2pack(n0, n1);
    ((unsigned*)qnh)[base+1] = h2pack(n2, n3);
    ((unsigned*)qsh)[base]   = h2pack((n0+qe4.x)*sp, (n1+qe4.y)*sp);
    ((unsigned*)qsh)[base+1] = h2pack((n2+qe4.z)*sp, (n3+qe4.w)*sp);

    __half2 ka = row[64 + 2*lane], kb = row[64 + 2*lane + 1];
    float k0 = __half2float(ka.x), k1 = __half2float(ka.y);
    float k2 = __half2float(kb.x), k3 = __half2float(kb.y);
    float ks = k0*k0 + k1*k1 + k2*k2 + k3*k3;
    ks += __shfl_xor_sync(0xffffffffu, ks, 1);
    ks += __shfl_xor_sync(0xffffffffu, ks, 2);
    ks += __shfl_xor_sync(0xffffffffu, ks, 4);
    float ki = 1.0f / fmaxf(sqrtf(ks), 1e-12f);
    ((unsigned*)klh)[base]   = h2pack(k0*ki, k1*ki);
    ((unsigned*)klh)[base+1] = h2pack(k2*ki, k3*ki);

    ((unsigned*)vlh)[base]   = *(const unsigned*)&row[128 + 2*lane];
    ((unsigned*)vlh)[base+1] = *(const unsigned*)&row[128 + 2*lane + 1];

    __half2 sa = row[192 + 2*lane], sb = row[192 + 2*lane + 1];
    float g0 = gelu_exact(__half2float(sa.x)), g1 = gelu_exact(__half2float(sa.y));
    float g2 = gelu_exact(__half2float(sb.x)), g3 = gelu_exact(__half2float(sb.y));
    float sm = g0+g1+g2+g3;
    float sq = g0*g0+g1*g1+g2*g2+g3*g3;
#pragma unroll
    for (int d = 1; d < 32; d <<= 1) {
        sm += __shfl_xor_sync(0xffffffffu, sm, d);
        sq += __shfl_xor_sync(0xffffffffu, sq, d);
    }
    float mu = sm*(1.0f/128.0f);
    float rstd = rsqrtf(sq*(1.0f/128.0f) - mu*mu + 1e-5f);
    int c = lane * 4;
    float o0 = (g0-mu)*rstd*plnw[c]   + plnb[c];
    float o1 = (g1-mu)*rstd*plnw[c+1] + plnb[c+1];
    float o2 = (g2-mu)*rstd*plnw[c+2] + plnb[c+2];
    float o3 = (g3-mu)*rstd*plnw[c+3] + plnb[c+3];
    unsigned* xh = (unsigned*)xph;
    xh[(size_t)t*64 + lane*2]     = h2pack(o0, o1);
    xh[(size_t)t*64 + lane*2 + 1] = h2pack(o2, o3);
}

// ---------- HMMA pooled attention (all-fp16 inputs) ----------
__global__ void __launch_bounds__(256) attn_pool_mma(
    const __half* __restrict__ qsh, const __half* __restrict__ kph,
    const __half* __restrict__ vph,
    const __half* __restrict__ qnh, const __half* __restrict__ klh,
    const __half* __restrict__ vlh, const float* __restrict__ lt,
    const float* __restrict__ lb,
    __half* __restrict__ atth)
{
    __shared__ __half Khi[128][40];
    __shared__ __half Vt[32][132];

    const int g  = blockIdx.y;
    const int tid = threadIdx.x;
    const int warp = tid >> 5;
    const int lane = tid & 31;
    const int r  = lane >> 2;
    const int c2 = (lane & 3) * 2;
    const int qbase = blockIdx.x * 128 + (warp >> 2) * 64 + (warp & 3) * 16 + r;
    const int qrow_l = (qbase < Nn) ? qbase : (Nn - 1);

    unsigned qhi[2][4];
    {
        const __half* q0p = qsh + ((size_t)g*Nn + qrow_l)*32;
        int q8c = (qbase + 8 < Nn) ? (qbase + 8) : (Nn - 1);
        const __half* q8p = qsh + ((size_t)g*Nn + q8c)*32;
#pragma unroll
        for (int ks = 0; ks < 2; ks++) {
            int d0 = ks*16 + c2;
            qhi[ks][0] = *(const unsigned*)&q0p[d0];
            qhi[ks][1] = *(const unsigned*)&q8p[d0];
            qhi[ks][2] = *(const unsigned*)&q0p[d0+8];
            qhi[ks][3] = *(const unsigned*)&q8p[d0+8];
        }
    }

    float uf[4][4];
#pragma unroll
    for (int t = 0; t < 4; t++)
#pragma unroll
        for (int i = 0; i < 4; i++) uf[t][i] = 0.f;
    float z0 = 0.f, z1 = 0.f;

    const int NCH = 25;
    for (int ch = 0; ch < NCH; ch++) {
        const int m0 = ch * 128;
        {
            int row = tid & 127;
            int hp  = tid >> 7;
            int kvr = m0 + row;
            bool ok = kvr < Nn;
            size_t rb = ((size_t)g*Nn + (ok ? kvr : 0))*32;
            const uint4* krh = (const uint4*)(kph + rb);
            uint4 z4 = make_uint4(0,0,0,0);
#pragma unroll
            for (int j = 0; j < 2; j++)
                *(uint4*)&Khi[row][(hp*2 + j)*8] = ok ? krh[hp*2 + j] : z4;
            const unsigned* vr = (const unsigned*)(vph + rb);
#pragma unroll
            for (int j = 0; j < 8; j++) {
                int jj = hp*8 + j;
                unsigned p = ok ? vr[jj] : 0u;
                __half2 hh = *(__half2*)&p;
                Vt[2*jj][row]   = hh.x;
                Vt[2*jj+1][row] = hh.y;
            }
        }
        __syncthreads();

        const int kkmax = (m0 + 128 <= Nn) ? 8 : 4;
        for (int kk = 0; kk < kkmax; kk++) {
            unsigned ea[4];
#pragma unroll
            for (int tt = 0; tt < 2; tt++) {
                int t = 2*kk + tt;
                int kv = t*8 + (lane >> 2);
                float sf[4] = {0.f, 0.f, 0.f, 0.f};
#pragma unroll
                for (int ks = 0; ks < 2; ks++) {
                    int d0 = ks*16 + c2;
                    unsigned bh0 = *(const unsigned*)&Khi[kv][d0];
                    unsigned bh1 = *(const unsigned*)&Khi[kv][d0+8];
                    mma16816(sf, qhi[ks], bh0, bh1);
                }
                float e0 = __expf(sf[0]);
                float e1 = __expf(sf[1]);
                float e2 = __expf(sf[2]);
                float e3 = __expf(sf[3]);
                z0 += e0 + e1;
                z1 += e2 + e3;
                ea[2*tt]   = h2pack(e0, e1);
                ea[2*tt+1] = h2pack(e2, e3);
            }
            int kv0 = kk*16 + c2;
#pragma unroll
            for (int nt = 0; nt < 4; nt++) {
                int d = nt*8 + (lane >> 2);
                unsigned b0 = *(const unsigned*)&Vt[d][kv0];
                unsigned b1 = *(const unsigned*)&Vt[d][kv0+8];
                mma16816(uf[nt], ea, b0, b1);
            }
        }
        __syncthreads();
    }

    // ---- fused finalize ----
    z0 += __shfl_xor_sync(0xffffffffu, z0, 1);
    z0 += __shfl_xor_sync(0xffffffffu, z0, 2);
    z1 += __shfl_xor_sync(0xffffffffu, z1, 1);
    z1 += __shfl_xor_sync(0xffffffffu, z1, 2);

    const int b = g >> 2, h = g & 3;
#pragma unroll
    for (int half = 0; half < 2; half++) {
        int n = qbase + half*8;
        bool nok = n < Nn;
        int nc = nok ? n : (Nn - 1);
        float Zpool = half ? z1 : z0;
        int hh = nc / Hs, ww = nc - hh*Hs;
        const __half* qp  = qsh + ((size_t)g*Nn + nc)*32;
        const __half* qnp = qnh + ((size_t)g*Nn + nc)*32;
        float qsv[8], qnv[8];
#pragma unroll
        for (int nt = 0; nt < 4; nt++) {
            int c = nt*8 + c2;
            __half2 a = *(const __half2*)&qp[c];
            __half2 bq = *(const __half2*)&qnp[c];
            qsv[nt*2]   = __half2float(a.x);  qsv[nt*2+1] = __half2float(a.y);
            qnv[nt*2]   = __half2float(bq.x); qnv[nt*2+1] = __half2float(bq.y);
        }
        float resv[8], res2v[8];
#pragma unroll
        for (int i = 0; i < 8; i++) { resv[i] = 0.f; res2v[i] = 0.f; }
        float zl = 0.f;
#pragma unroll
        for (int k = 0; k < 9; k++) {
            int h2 = hh + k/3 - 1, w2 = ww + (k%3) - 1;
            bool ok = (h2 >= 0 && h2 < Hs && w2 >= 0 && w2 < Hs);
            size_t bi = ((size_t)g*Nn + (ok ? (h2*Hs + w2) : 0))*32;
            float klv[8], vlv[8];
            float lg = 0.f, wl = 0.f;
#pragma unroll
            for (int nt = 0; nt < 4; nt++) {
                int c = nt*8 + c2;
                __half2 kk2 = ok ? *(const __half2*)&klh[bi + c] : __half2(__float2half(0.f), __float2half(0.f));
                __half2 vv2 = ok ? *(const __half2*)&vlh[bi + c] : __half2(__float2half(0.f), __float2half(0.f));
                int idx = nt*2;
                klv[idx]   = __half2float(kk2.x); klv[idx+1] = __half2float(kk2.y);
                vlv[idx]   = __half2float(vv2.x); vlv[idx+1] = __half2float(vv2.y);
                lg += qsv[idx]*klv[idx] + qsv[idx+1]*klv[idx+1];
                wl += qnv[idx]*lt[(h*32 + c)*9 + k] + qnv[idx+1]*lt[(h*32 + c + 1)*9 + k];
            }
            lg += __shfl_xor_sync(0xffffffffu, lg, 1);
            lg += __shfl_xor_sync(0xffffffffu, lg, 2);
            wl += __shfl_xor_sync(0xffffffffu, wl, 1);
            wl += __shfl_xor_sync(0xffffffffu, wl, 2);
            float e = __expf(lg);
            zl += e;
            float w2l = wl + lb[h*9 + k];
#pragma unroll
            for (int i = 0; i < 8; i++) {
                resv[i]  += e   * vlv[i];
                res2v[i] += w2l * vlv[i];
            }
        }
        float Zf = Zpool + zl;
        float rZ = 1.0f / Zf;
        if (nok) {
#pragma unroll
            for (int nt = 0; nt < 4; nt++)
#pragma unroll
                for (int j = 0; j < 2; j++) {
                    int c = nt*8 + c2 + j;
                    int idx = nt*2 + j;
                    float o = (uf[nt][half*2 + j] + resv[idx]) * rZ + res2v[idx];
                    size_t oi = ((size_t)(b*Nn + n))*128 + h*32 + c;
                    atth[oi] = __float2half_rn(o);
                }
        }
    }
}

// ---------- tiled depthwise 3x3 + gelu * v: row x 64-ch chunk, smem halo ----------
__global__ void __launch_bounds__(256) dwconv_kernel(
    const __half* __restrict__ f1, const float* __restrict__ dww,
    const float* __restrict__ dwb, __half* __restrict__ gbh)
{
    __shared__ __half S[3][58][64];
    const int rr = blockIdx.x;                 // 0..111
    const int b  = rr / Hs, hh = rr - b*Hs;
    const int cbase = blockIdx.y * 64;
    const int tid = threadIdx.x;
    const int ch = tid & 63;
    const int colg = tid >> 6;                 // 0..3
    const int c = cbase + ch;

    // stage 3x58x64 halo tile
    for (int i = tid; i < 3*58*64; i += 256) {
        int cc = i & 63;
        int ci = (i >> 6) % 58;
        int rowi = (i >> 6) / 58;
        int h2 = hh + rowi - 1;
        int col = ci - 1;
        int gc = cbase + cc;
        __half v = __float2half(0.f);
        if (h2 >= 0 && h2 < Hs && col >= 0 && col < Hs && gc < HFn)
            v = f1[((size_t)(b*Nn + h2*Hs + col))*682 + gc];
        S[rowi][ci][cc] = v;
    }
    __syncthreads();

    if (c >= LDF) return;
    if (c >= HFn) {
        // zero padded region of gbh
        __half z = __float2half(0.f);
#pragma unroll
        for (int j = 0; j < 14; j++) {
            int col = colg + 4*j;
            gbh[(size_t)(b*Nn + hh*Hs + col)*LDF + c] = z;
        }
        return;
    }

    float w[9];
#pragma unroll
    for (int k = 0; k < 9; k++) w[k] = dww[c*9 + k];
    float bias = dwb[c];

#pragma unroll
    for (int j = 0; j < 14; j++) {
        int col = colg + 4*j;                  // 0..55
        int t = b*Nn + hh*Hs + col;
        float acc = bias;
#pragma unroll
        for (int k = 0; k < 9; k++)
            acc += __half2float(S[k/3][col + (k%3)][ch]) * w[k];
        float v = __half2float(f1[(size_t)t*682 + 341 + c]);
        gbh[(size_t)t*LDF + c] = __float2half_rn(gelu_exact(acc) * v);
    }
}

extern "C" void kernel_launch(void* const* d_in, const int* in_sizes, int n_in,
                              void* d_out, int out_size)
{
    const float* x      = (const float*)d_in[0];
    const float* n1w    = (const float*)d_in[1];
    const float* n1b    = (const float*)d_in[2];
    const float* q_w    = (const float*)d_in[3];
    const float* q_b    = (const float*)d_in[4];
    const float* kv_w   = (const float*)d_in[5];
    const float* kv_b   = (const float*)d_in[6];
    const float* temp   = (const float*)d_in[7];
    const float* qe     = (const float*)d_in[8];
    const float* lt     = (const float*)d_in[9];
    const float* lb     = (const float*)d_in[10];
    const float* sr_w   = (const float*)d_in[11];
    const float* sr_b   = (const float*)d_in[12];
    const float* plnw   = (const float*)d_in[13];
    const float* plnb   = (const float*)d_in[14];
    const float* proj_w = (const float*)d_in[15];
    const float* proj_b = (const float*)d_in[16];
    const float* n2w    = (const float*)d_in[17];
    const float* n2b    = (const float*)d_in[18];
    const float* fc1_w  = (const float*)d_in[19];
    const float* fc1_b  = (const float*)d_in[20];
    const float* dw_w   = (const float*)d_in[21];
    const float* dw_b   = (const float*)d_in[22];
    const float* fc2_w  = (const float*)d_in[23];
    const float* fc2_b  = (const float*)d_in[24];
    float* out = (float*)d_out;

    float *x2b, *b512;
    __half *t1h, *qshb, *qnhb, *klhb, *vlhb, *f1hb, *yh, *xph, *atth, *y2h, *kph, *vphh, *gbh, *wh;
    cudaGetSymbolAddress((void**)&x2b,  g_x2);
    cudaGetSymbolAddress((void**)&b512, g_b512);
    cudaGetSymbolAddress((void**)&t1h,  g_t1h);
    cudaGetSymbolAddress((void**)&qshb, g_qsh);
    cudaGetSymbolAddress((void**)&qnhb, g_qnh);
    cudaGetSymbolAddress((void**)&klhb, g_klh);
    cudaGetSymbolAddress((void**)&vlhb, g_vlh);
    cudaGetSymbolAddress((void**)&f1hb, g_f1h);
    cudaGetSymbolAddress((void**)&yh,   g_yh);
    cudaGetSymbolAddress((void**)&xph,  g_xph);
    cudaGetSymbolAddress((void**)&atth, g_atth);
    cudaGetSymbolAddress((void**)&y2h,  g_y2h);
    cudaGetSymbolAddress((void**)&kph,  g_kph);
    cudaGetSymbolAddress((void**)&vphh, g_vph);
    cudaGetSymbolAddress((void**)&gbh,  g_gbh);
    cudaGetSymbolAddress((void**)&wh,   g_wh);

    cvt_all<<<840, 256>>>(q_w, kv_w, sr_w, proj_w, fc1_w, fc2_w, q_b, kv_b, sr_b, wh, b512);

    ln_kernel<<<TOK/8, 256>>>(x, n1w, n1b, yh);
    hgemm2<<<dim3(8,98), 128>>>(yh, wh+OQ, 128, b512, (float*)t1h, 512, 512, 3, nullptr);
    pointwise1<<<TOK/8, 256>>>(t1h, temp, qe, plnw, plnb, qshb, qnhb, klhb, vlhb, xph);
    hgemm_kv<<<dim3(4,98), 128>>>(xph, wh+OKV, kv_b, kph, vphh);
    attn_pool_mma<<<dim3(25,8), 256>>>(qshb, kph, vphh, qnhb, klhb, vlhb, lt, lb, atth);
    hgemm2<<<dim3(2,98), 128>>>(atth, wh+OPJ, 128, proj_b, x2b, 128, 128, 1, x);
    ln_kernel<<<TOK/8, 256>>>(x2b, n2w, n2b, y2h);
    hgemm2<<<dim3(11,98), 128>>>(y2h, wh+OF1, 128, fc1_b, (float*)f1hb, 682, 682, 3, nullptr);
    dwconv_kernel<<<dim3(112,6), 256>>>(f1hb, dw_w, dw_b, gbh);
    hgemm2<<<dim3(2,98), 128>>>(gbh, wh+OF2, LDF, fc2_b, out, 128, 128, 2, x2b);
}

// round 15
// speedup vs baseline: 1.0516x; 1.0516x over previous
#include <cuda_runtime.h>
#include <cuda_fp16.h>
#include <math.h>

#define Bn   2
#define Cn   128
#define Hs   56
#define Nn   3136
#define NHn  4
#define HFn  341
#define TOK  (Bn*Nn)
#define LDF  352
#define LOG2E 1.4426950408889634f

// fp32 scratch
__device__ __align__(256) float g_x2 [TOK*Cn];
__device__ __align__(256) float g_b512[512];
// half scratch
__device__ __align__(256) __half g_t1h[TOK*512];
__device__ __align__(256) __half g_qsh[8*Nn*32];
__device__ __align__(256) __half g_qnh[8*Nn*32];
__device__ __align__(256) __half g_klh[8*Nn*32];
__device__ __align__(256) __half g_vlh[8*Nn*32];
__device__ __align__(256) __half g_f1h[TOK*682];
__device__ __align__(256) __half g_yh [TOK*Cn];
__device__ __align__(256) __half g_xph[TOK*Cn];
__device__ __align__(256) __half g_atth[TOK*Cn];
__device__ __align__(256) __half g_y2h[TOK*Cn];
__device__ __align__(256) __half g_kph[TOK*Cn];
__device__ __align__(256) __half g_vph[TOK*Cn];
__device__ __align__(256) __half g_gbh[TOK*LDF];
// converted weights pool (hi only)
#define OQ   0
#define OKV  16384
#define OSR  49152
#define OPJ  65536
#define OF1  81920
#define OF2  169216
#define WTOT 214272
__device__ __align__(256) __half g_wh[WTOT];

__device__ __forceinline__ float gelu_exact(float x) {
    return 0.5f * x * (1.0f + erff(x * 0.70710678118654752f));
}
__device__ __forceinline__ unsigned h2pack(float a, float b) {
    __half2 h = __floats2half2_rn(a, b);
    return *(unsigned*)&h;
}
__device__ __forceinline__ unsigned ex2_h2(unsigned x) {
    unsigned d;
    asm("ex2.approx.f16x2 %0, %1;" : "=r"(d) : "r"(x));
    return d;
}
__device__ __forceinline__ void mma16816(float* c, const unsigned* a, unsigned b0, unsigned b1) {
    asm volatile("mma.sync.aligned.m16n8k16.row.col.f32.f16.f16.f32 "
        "{%0,%1,%2,%3}, {%4,%5,%6,%7}, {%8,%9}, {%0,%1,%2,%3};"
        : "+f"(c[0]), "+f"(c[1]), "+f"(c[2]), "+f"(c[3])
        : "r"(a[0]), "r"(a[1]), "r"(a[2]), "r"(a[3]), "r"(b0), "r"(b1));
}

// ---------- single-launch weight conversion (hi only) + fused bias ----------
__global__ void cvt_all(const float* __restrict__ q_w, const float* __restrict__ kv_w,
                        const float* __restrict__ sr_w, const float* __restrict__ proj_w,
                        const float* __restrict__ fc1_w, const float* __restrict__ fc2_w,
                        const float* __restrict__ q_b, const float* __restrict__ kv_b,
                        const float* __restrict__ sr_b,
                        __half* __restrict__ wh, float* __restrict__ b512)
{
    int i = blockIdx.x * 256 + threadIdx.x;
    if (i < WTOT) {
        float v;
        if      (i < OKV) v = q_w[i];
        else if (i < OSR) v = kv_w[i - OKV];
        else if (i < OPJ) v = sr_w[i - OSR];
        else if (i < OF1) v = proj_w[i - OPJ];
        else if (i < OF2) v = fc1_w[i - OF1];
        else {
            int j = i - OF2, r = j / LDF, c = j - r * LDF;
            v = (c < HFn) ? fc2_w[r * HFn + c] : 0.f;
        }
        wh[i] = __float2half_rn(v);
    } else if (i < WTOT + 512) {
        int j = i - WTOT;
        b512[j] = (j < 128) ? q_b[j] : (j < 384) ? kv_b[j - 128] : sr_b[j - 384];
    }
}

// ---------- LayerNorm (channel-major in) -> fp16 token-major ----------
__global__ void ln_kernel(const float* __restrict__ in, const float* __restrict__ w,
                          const float* __restrict__ bvec, __half* __restrict__ oh)
{
    int warp = blockIdx.x * 8 + (threadIdx.x >> 5);
    int lane = threadIdx.x & 31;
    int bb = warp / Nn, n = warp - bb * Nn;
    const float* p = in + (size_t)bb * (Cn*Nn) + n;
    float v[4], s = 0.f, s2 = 0.f;
#pragma unroll
    for (int pp = 0; pp < 2; pp++) {
        int c0 = 2*lane + 64*pp;
        v[2*pp]   = p[(size_t)c0 * Nn];
        v[2*pp+1] = p[(size_t)(c0+1) * Nn];
        s += v[2*pp] + v[2*pp+1];
        s2 += v[2*pp]*v[2*pp] + v[2*pp+1]*v[2*pp+1];
    }
#pragma unroll
    for (int d = 1; d < 32; d <<= 1) {
        s  += __shfl_xor_sync(0xffffffffu, s,  d);
        s2 += __shfl_xor_sync(0xffffffffu, s2, d);
    }
    float mu = s * (1.0f/128.0f);
    float rstd = rsqrtf(s2*(1.0f/128.0f) - mu*mu + 1e-5f);
    unsigned* ohp = (unsigned*)oh;
#pragma unroll
    for (int pp = 0; pp < 2; pp++) {
        int c0 = 2*lane + 64*pp;
        float a = (v[2*pp]  -mu)*rstd*w[c0]   + bvec[c0];
        float b = (v[2*pp+1]-mu)*rstd*w[c0+1] + bvec[c0+1];
        ohp[warp*64 + lane + 32*pp] = h2pack(a, b);
    }
}

// ---------- HMMA GEMM: single fp16 A x W ----------
// mode 0: fp32 out; 1: fp32 +res; 2: transposed channel-major +res; 3: fp16 out
__global__ void __launch_bounds__(128) hgemm2(
    const __half* __restrict__ Ah, const __half* __restrict__ Wh, int ld,
    const float* __restrict__ bias, float* __restrict__ out,
    int ldo, int Nout, int mode, const float* __restrict__ res)
{
    const int m0 = blockIdx.y * 64;
    const int n0 = blockIdx.x * 64;
    const int warp = threadIdx.x >> 5;
    const int lane = threadIdx.x & 31;
    const int r  = lane >> 2;
    const int c2 = (lane & 3) * 2;

    float acc[8][4];
#pragma unroll
    for (int t = 0; t < 8; t++)
#pragma unroll
        for (int i = 0; i < 4; i++) acc[t][i] = 0.f;

    const int row1 = m0 + warp*16 + r;
    const __half* a1h = Ah + (size_t)row1 * ld;
    const __half* a2h = a1h + (size_t)8 * ld;

    const int nr = n0 + (lane >> 2);
    const __half* wrow[8];
#pragma unroll
    for (int nt = 0; nt < 8; nt++) {
        int n = nr + nt*8;
        int nc = (n < Nout) ? n : (Nout - 1);
        wrow[nt] = Wh + (size_t)nc * ld;
    }

    const int KC = ld / 32;
    for (int kc = 0; kc < KC; kc++) {
#pragma unroll
        for (int ks = 0; ks < 2; ks++) {
            int d0 = kc*32 + ks*16 + c2;
            unsigned ah[4];
            ah[0] = *(const unsigned*)&a1h[d0];
            ah[1] = *(const unsigned*)&a2h[d0];
            ah[2] = *(const unsigned*)&a1h[d0+8];
            ah[3] = *(const unsigned*)&a2h[d0+8];
#pragma unroll
            for (int nt = 0; nt < 8; nt++) {
                unsigned bh0 = *(const unsigned*)&wrow[nt][d0];
                unsigned bh1 = *(const unsigned*)&wrow[nt][d0+8];
                mma16816(acc[nt], ah, bh0, bh1);
            }
        }
    }

    int m1 = row1, m2 = row1 + 8;
#pragma unroll
    for (int nt = 0; nt < 8; nt++) {
        int n = n0 + nt*8 + c2;
#pragma unroll
        for (int j = 0; j < 2; j++) {
            int nn = n + j;
            if (nn >= Nout) continue;
            float v1 = acc[nt][j]   + bias[nn];
            float v2 = acc[nt][2+j] + bias[nn];
            if (mode == 0) {
                out[(size_t)m1*ldo + nn] = v1;
                out[(size_t)m2*ldo + nn] = v2;
            } else if (mode == 1) {
                size_t i1 = (size_t)m1*ldo + nn, i2 = (size_t)m2*ldo + nn;
                out[i1] = v1 + res[i1];
                out[i2] = v2 + res[i2];
            } else if (mode == 2) {
                int b1 = m1 / Nn, t1i = m1 - b1*Nn;
                int b2 = m2 / Nn, t2i = m2 - b2*Nn;
                size_t i1 = ((size_t)b1*Cn + nn)*Nn + t1i;
                size_t i2 = ((size_t)b2*Cn + nn)*Nn + t2i;
                out[i1] = v1 + res[i1];
                out[i2] = v2 + res[i2];
            } else {
                __half* oh = (__half*)out;
                oh[(size_t)m1*ldo + nn] = __float2half_rn(v1);
                oh[(size_t)m2*ldo + nn] = __float2half_rn(v2);
            }
        }
    }
}

// ---------- HMMA kv GEMM with fused l2norm/split epilogue -> kph/vph fp16 ----------
__global__ void __launch_bounds__(128) hgemm_kv(
    const __half* __restrict__ Ah, const __half* __restrict__ Wh,
    const float* __restrict__ bias,
    __half* __restrict__ kph, __half* __restrict__ vph)
{
    const int m0 = blockIdx.y * 64;
    const int n0 = blockIdx.x * 64;
    const int warp = threadIdx.x >> 5;
    const int lane = threadIdx.x & 31;
    const int r  = lane >> 2;
    const int c2 = (lane & 3) * 2;
    const int ld = 128;

    float acc[8][4];
#pragma unroll
    for (int t = 0; t < 8; t++)
#pragma unroll
        for (int i = 0; i < 4; i++) acc[t][i] = 0.f;

    const int row1 = m0 + warp*16 + r;
    const __half* a1h = Ah + (size_t)row1 * ld;
    const __half* a2h = a1h + (size_t)8 * ld;

    const int nr = n0 + (lane >> 2);
    const __half* wrow[8];
#pragma unroll
    for (int nt = 0; nt < 8; nt++)
        wrow[nt] = Wh + (size_t)(nr + nt*8) * ld;

#pragma unroll
    for (int kc = 0; kc < 4; kc++) {
#pragma unroll
        for (int ks = 0; ks < 2; ks++) {
            int d0 = kc*32 + ks*16 + c2;
            unsigned ah[4];
            ah[0] = *(const unsigned*)&a1h[d0];
            ah[1] = *(const unsigned*)&a2h[d0];
            ah[2] = *(const unsigned*)&a1h[d0+8];
            ah[3] = *(const unsigned*)&a2h[d0+8];
#pragma unroll
            for (int nt = 0; nt < 8; nt++) {
                unsigned bh0 = *(const unsigned*)&wrow[nt][d0];
                unsigned bh1 = *(const unsigned*)&wrow[nt][d0+8];
                mma16816(acc[nt], ah, bh0, bh1);
            }
        }
    }

#pragma unroll
    for (int half = 0; half < 2; half++) {
        int m = row1 + half*8;
        int bb = m / Nn, n = m - bb*Nn;
        float vals[16];
#pragma unroll
        for (int nt = 0; nt < 8; nt++)
#pragma unroll
            for (int j = 0; j < 2; j++)
                vals[nt*2+j] = acc[nt][half*2+j] + bias[n0 + nt*8 + c2 + j];
        if (n0 < 128) {
            float se = 0.f, so = 0.f;
#pragma unroll
            for (int i = 0; i < 8; i++) { se += vals[i]*vals[i]; so += vals[8+i]*vals[8+i]; }
            se += __shfl_xor_sync(0xffffffffu, se, 1);
            se += __shfl_xor_sync(0xffffffffu, se, 2);
            so += __shfl_xor_sync(0xffffffffu, so, 1);
            so += __shfl_xor_sync(0xffffffffu, so, 2);
            float ke = 1.0f / fmaxf(sqrtf(se), 1e-12f);
            float ko = 1.0f / fmaxf(sqrtf(so), 1e-12f);
#pragma unroll
            for (int nt = 0; nt < 8; nt++) {
                int col = n0 + nt*8 + c2;
                int head = col >> 5;
                float sc = (nt < 4) ? ke : ko;
                __half2 hv = __floats2half2_rn(vals[nt*2]*sc, vals[nt*2+1]*sc);
                *(__half2*)&kph[((size_t)(bb*NHn + head)*Nn + n)*32 + (col & 31)] = hv;
            }
        } else {
#pragma unroll
            for (int nt = 0; nt < 8; nt++) {
                int col = n0 - 128 + nt*8 + c2;
                int head = col >> 5;
                __half2 hv = __floats2half2_rn(vals[nt*2], vals[nt*2+1]);
                *(__half2*)&vph[((size_t)(bb*NHn + head)*Nn + n)*32 + (col & 31)] = hv;
            }
        }
    }
}

// ---------- pointwise after fused QKVSR GEMM (qs pre-scaled by log2e) ----------
__global__ void pointwise1(const __half* __restrict__ t1h, const float* __restrict__ temp,
                           const float* __restrict__ qe, const float* __restrict__ plnw,
                           const float* __restrict__ plnb,
                           __half* __restrict__ qsh, __half* __restrict__ qnh,
                           __half* __restrict__ klh, __half* __restrict__ vlh,
                           __half* __restrict__ xph)
{
    int t = blockIdx.x * 8 + (threadIdx.x >> 5);
    int lane = threadIdx.x & 31;
    int bb = t / Nn, n = t - bb * Nn;
    int h = lane >> 3;
    int g = bb * NHn + h;
    const __half2* row = (const __half2*)(t1h + (size_t)t * 512);
    unsigned base = ((unsigned)g*Nn + n)*16 + (lane & 7)*2;

    __half2 qa = row[2*lane], qb = row[2*lane + 1];
    float q0 = __half2float(qa.x), q1 = __half2float(qa.y);
    float q2 = __half2float(qb.x), q3 = __half2float(qb.y);
    float ss = q0*q0 + q1*q1 + q2*q2 + q3*q3;
    ss += __shfl_xor_sync(0xffffffffu, ss, 1);
    ss += __shfl_xor_sync(0xffffffffu, ss, 2);
    ss += __shfl_xor_sync(0xffffffffu, ss, 4);
    float inv = 1.0f / fmaxf(sqrtf(ss), 1e-12f);
    float n0 = q0*inv, n1 = q1*inv, n2 = q2*inv, n3 = q3*inv;
    float tv = temp[h];
    float sp = log1pf(__expf(tv)) * LOG2E;   // pooled+local logits move to log2 domain
    float4 qe4 = ((const float4*)qe)[h*8 + (lane & 7)];
    ((unsigned*)qnh)[base]   = h2pack(n0, n1);
    ((unsigned*)qnh)[base+1] = h2pack(n2, n3);
    ((unsigned*)qsh)[base]   = h2pack((n0+qe4.x)*sp, (n1+qe4.y)*sp);
    ((unsigned*)qsh)[base+1] = h2pack((n2+qe4.z)*sp, (n3+qe4.w)*sp);

    __half2 ka = row[64 + 2*lane], kb = row[64 + 2*lane + 1];
    float k0 = __half2float(ka.x), k1 = __half2float(ka.y);
    float k2 = __half2float(kb.x), k3 = __half2float(kb.y);
    float ks = k0*k0 + k1*k1 + k2*k2 + k3*k3;
    ks += __shfl_xor_sync(0xffffffffu, ks, 1);
    ks += __shfl_xor_sync(0xffffffffu, ks, 2);
    ks += __shfl_xor_sync(0xffffffffu, ks, 4);
    float ki = 1.0f / fmaxf(sqrtf(ks), 1e-12f);
    ((unsigned*)klh)[base]   = h2pack(k0*ki, k1*ki);
    ((unsigned*)klh)[base+1] = h2pack(k2*ki, k3*ki);

    ((unsigned*)vlh)[base]   = *(const unsigned*)&row[128 + 2*lane];
    ((unsigned*)vlh)[base+1] = *(const unsigned*)&row[128 + 2*lane + 1];

    __half2 sa = row[192 + 2*lane], sb = row[192 + 2*lane + 1];
    float g0 = gelu_exact(__half2float(sa.x)), g1 = gelu_exact(__half2float(sa.y));
    float g2 = gelu_exact(__half2float(sb.x)), g3 = gelu_exact(__half2float(sb.y));
    float sm = g0+g1+g2+g3;
    float sq = g0*g0+g1*g1+g2*g2+g3*g3;
#pragma unroll
    for (int d = 1; d < 32; d <<= 1) {
        sm += __shfl_xor_sync(0xffffffffu, sm, d);
        sq += __shfl_xor_sync(0xffffffffu, sq, d);
    }
    float mu = sm*(1.0f/128.0f);
    float rstd = rsqrtf(sq*(1.0f/128.0f) - mu*mu + 1e-5f);
    int c = lane * 4;
    float o0 = (g0-mu)*rstd*plnw[c]   + plnb[c];
    float o1 = (g1-mu)*rstd*plnw[c+1] + plnb[c+1];
    float o2 = (g2-mu)*rstd*plnw[c+2] + plnb[c+2];
    float o3 = (g3-mu)*rstd*plnw[c+3] + plnb[c+3];
    unsigned* xh = (unsigned*)xph;
    xh[(size_t)t*64 + lane*2]     = h2pack(o0, o1);
    xh[(size_t)t*64 + lane*2 + 1] = h2pack(o2, o3);
}

// ---------- HMMA pooled attention: ex2.f16x2 + Z-via-ones-column ----------
__global__ void __launch_bounds__(256) attn_pool_mma(
    const __half* __restrict__ qsh, const __half* __restrict__ kph,
    const __half* __restrict__ vph,
    const __half* __restrict__ qnh, const __half* __restrict__ klh,
    const __half* __restrict__ vlh, const float* __restrict__ lt,
    const float* __restrict__ lb,
    __half* __restrict__ atth)
{
    __shared__ __half Khi[128][40];
    __shared__ __half Vt[40][132];   // rows 0-31 = V^T, row 32 = valid-mask ones, 33-39 = 0

    const int g  = blockIdx.y;
    const int tid = threadIdx.x;
    const int warp = tid >> 5;
    const int lane = tid & 31;
    const int r  = lane >> 2;
    const int c2 = (lane & 3) * 2;
    const int qbase = blockIdx.x * 128 + (warp >> 2) * 64 + (warp & 3) * 16 + r;
    const int qrow_l = (qbase < Nn) ? qbase : (Nn - 1);

    unsigned qhi[2][4];
    {
        const __half* q0p = qsh + ((size_t)g*Nn + qrow_l)*32;
        int q8c = (qbase + 8 < Nn) ? (qbase + 8) : (Nn - 1);
        const __half* q8p = qsh + ((size_t)g*Nn + q8c)*32;
#pragma unroll
        for (int ks = 0; ks < 2; ks++) {
            int d0 = ks*16 + c2;
            qhi[ks][0] = *(const unsigned*)&q0p[d0];
            qhi[ks][1] = *(const unsigned*)&q8p[d0];
            qhi[ks][2] = *(const unsigned*)&q0p[d0+8];
            qhi[ks][3] = *(const unsigned*)&q8p[d0+8];
        }
    }

    float uf[5][4];
#pragma unroll
    for (int t = 0; t < 5; t++)
#pragma unroll
        for (int i = 0; i < 4; i++) uf[t][i] = 0.f;

    const int NCH = 25;
    for (int ch = 0; ch < NCH; ch++) {
        const int m0 = ch * 128;
        {
            int row = tid & 127;
            int hp  = tid >> 7;
            int kvr = m0 + row;
            bool ok = kvr < Nn;
            size_t rb = ((size_t)g*Nn + (ok ? kvr : 0))*32;
            const uint4* krh = (const uint4*)(kph + rb);
            uint4 z4 = make_uint4(0,0,0,0);
#pragma unroll
            for (int j = 0; j < 2; j++)
                *(uint4*)&Khi[row][(hp*2 + j)*8] = ok ? krh[hp*2 + j] : z4;
            const unsigned* vr = (const unsigned*)(vph + rb);
#pragma unroll
            for (int j = 0; j < 8; j++) {
                int jj = hp*8 + j;
                unsigned p = ok ? vr[jj] : 0u;
                __half2 hh = *(__half2*)&p;
                Vt[2*jj][row]   = hh.x;
                Vt[2*jj+1][row] = hh.y;
            }
            // ones-mask column (row 32) and zero rows 33-39
#pragma unroll
            for (int j = 0; j < 4; j++) {
                int d = 32 + hp*4 + j;
                Vt[d][row] = (d == 32 && ok) ? __float2half(1.f) : __float2half(0.f);
            }
        }
        __syncthreads();

        const int kkmax = (m0 + 128 <= Nn) ? 8 : 4;
        for (int kk = 0; kk < kkmax; kk++) {
            unsigned ea[4];
#pragma unroll
            for (int tt = 0; tt < 2; tt++) {
                int t = 2*kk + tt;
                int kv = t*8 + (lane >> 2);
                float sf[4] = {0.f, 0.f, 0.f, 0.f};
#pragma unroll
                for (int ks = 0; ks < 2; ks++) {
                    int d0 = ks*16 + c2;
                    unsigned bh0 = *(const unsigned*)&Khi[kv][d0];
                    unsigned bh1 = *(const unsigned*)&Khi[kv][d0+8];
                    mma16816(sf, qhi[ks], bh0, bh1);
                }
                // logits already log2-domain -> pack then one f16x2 EX2 each
                ea[2*tt]   = ex2_h2(h2pack(sf[0], sf[1]));
                ea[2*tt+1] = ex2_h2(h2pack(sf[2], sf[3]));
            }
            int kv0 = kk*16 + c2;
#pragma unroll
            for (int nt = 0; nt < 5; nt++) {
                int d = nt*8 + (lane >> 2);
                unsigned b0 = *(const unsigned*)&Vt[d][kv0];
                unsigned b1 = *(const unsigned*)&Vt[d][kv0+8];
                mma16816(uf[nt], ea, b0, b1);
            }
        }
        __syncthreads();
    }

    // Z sits at col 32 (n-tile 4, tile-col 0) held by quad-base lane
    float z0 = __shfl_sync(0xffffffffu, uf[4][0], lane & 28);
    float z1 = __shfl_sync(0xffffffffu, uf[4][2], lane & 28);

    const int b = g >> 2, h = g & 3;
#pragma unroll
    for (int half = 0; half < 2; half++) {
        int n = qbase + half*8;
        bool nok = n < Nn;
        int nc = nok ? n : (Nn - 1);
        float Zpool = half ? z1 : z0;
        int hh = nc / Hs, ww = nc - hh*Hs;
        const __half* qp  = qsh + ((size_t)g*Nn + nc)*32;
        const __half* qnp = qnh + ((size_t)g*Nn + nc)*32;
        float qsv[8], qnv[8];
#pragma unroll
        for (int nt = 0; nt < 4; nt++) {
            int c = nt*8 + c2;
            __half2 a = *(const __half2*)&qp[c];
            __half2 bq = *(const __half2*)&qnp[c];
            qsv[nt*2]   = __half2float(a.x);  qsv[nt*2+1] = __half2float(a.y);
            qnv[nt*2]   = __half2float(bq.x); qnv[nt*2+1] = __half2float(bq.y);
        }
        float resv[8], res2v[8];
#pragma unroll
        for (int i = 0; i < 8; i++) { resv[i] = 0.f; res2v[i] = 0.f; }
        float zl = 0.f;
#pragma unroll
        for (int k = 0; k < 9; k++) {
            int h2 = hh + k/3 - 1, w2 = ww + (k%3) - 1;
            bool ok = (h2 >= 0 && h2 < Hs && w2 >= 0 && w2 < Hs);
            size_t bi = ((size_t)g*Nn + (ok ? (h2*Hs + w2) : 0))*32;
            float klv[8], vlv[8];
            float lg = 0.f, wl = 0.f;
#pragma unroll
            for (int nt = 0; nt < 4; nt++) {
                int c = nt*8 + c2;
                __half2 kk2 = ok ? *(const __half2*)&klh[bi + c] : __half2(__float2half(0.f), __float2half(0.f));
                __half2 vv2 = ok ? *(const __half2*)&vlh[bi + c] : __half2(__float2half(0.f), __float2half(0.f));
                int idx = nt*2;
                klv[idx]   = __half2float(kk2.x); klv[idx+1] = __half2float(kk2.y);
                vlv[idx]   = __half2float(vv2.x); vlv[idx+1] = __half2float(vv2.y);
                lg += qsv[idx]*klv[idx] + qsv[idx+1]*klv[idx+1];
                wl += qnv[idx]*lt[(h*32 + c)*9 + k] + qnv[idx+1]*lt[(h*32 + c + 1)*9 + k];
            }
            lg += __shfl_xor_sync(0xffffffffu, lg, 1);
            lg += __shfl_xor_sync(0xffffffffu, lg, 2);
            wl += __shfl_xor_sync(0xffffffffu, wl, 1);
            wl += __shfl_xor_sync(0xffffffffu, wl, 2);
            float e = exp2f(lg);            // qs pre-scaled by log2e
            zl += e;
            float w2l = wl + lb[h*9 + k];
#pragma unroll
            for (int i = 0; i < 8; i++) {
                resv[i]  += e   * vlv[i];
                res2v[i] += w2l * vlv[i];
            }
        }
        float Zf = Zpool + zl;
        float rZ = 1.0f / Zf;
        if (nok) {
#pragma unroll
            for (int nt = 0; nt < 4; nt++)
#pragma unroll
                for (int j = 0; j < 2; j++) {
                    int c = nt*8 + c2 + j;
                    int idx = nt*2 + j;
                    float o = (uf[nt][half*2 + j] + resv[idx]) * rZ + res2v[idx];
                    size_t oi = ((size_t)(b*Nn + n))*128 + h*32 + c;
                    atth[oi] = __float2half_rn(o);
                }
        }
    }
}

// ---------- depthwise 3x3 + gelu * v (fp16 f1) -> fp16 (R13 version) ----------
__global__ void dwconv_kernel(const __half* __restrict__ f1, const float* __restrict__ dww,
                              const float* __restrict__ dwb, __half* __restrict__ gbh)
{
    int t = blockIdx.x;
    int c = threadIdx.x;
    if (c >= LDF) return;
    size_t oi = (size_t)t*LDF + c;
    if (c >= HFn) { gbh[oi] = __float2half(0.f); return; }
    int b = t / Nn, n = t - b*Nn;
    int hh = n / Hs, ww = n - hh*Hs;
    float acc = dwb[c];
#pragma unroll
    for (int k = 0; k < 9; k++) {
        int h2 = hh + k/3 - 1, w2 = ww + (k%3) - 1;
        if (h2 < 0 || h2 >= Hs || w2 < 0 || w2 >= Hs) continue;
        acc += __half2float(f1[((size_t)(b*Nn + h2*Hs + w2))*682 + c]) * dww[c*9 + k];
    }
    float v = __half2float(f1[(size_t)t*682 + 341 + c]);
    gbh[oi] = __float2half_rn(gelu_exact(acc) * v);
}

extern "C" void kernel_launch(void* const* d_in, const int* in_sizes, int n_in,
                              void* d_out, int out_size)
{
    const float* x      = (const float*)d_in[0];
    const float* n1w    = (const float*)d_in[1];
    const float* n1b    = (const float*)d_in[2];
    const float* q_w    = (const float*)d_in[3];
    const float* q_b    = (const float*)d_in[4];
    const float* kv_w   = (const float*)d_in[5];
    const float* kv_b   = (const float*)d_in[6];
    const float* temp   = (const float*)d_in[7];
    const float* qe     = (const float*)d_in[8];
    const float* lt     = (const float*)d_in[9];
    const float* lb     = (const float*)d_in[10];
    const float* sr_w   = (const float*)d_in[11];
    const float* sr_b   = (const float*)d_in[12];
    const float* plnw   = (const float*)d_in[13];
    const float* plnb   = (const float*)d_in[14];
    const float* proj_w = (const float*)d_in[15];
    const float* proj_b = (const float*)d_in[16];
    const float* n2w    = (const float*)d_in[17];
    const float* n2b    = (const float*)d_in[18];
    const float* fc1_w  = (const float*)d_in[19];
    const float* fc1_b  = (const float*)d_in[20];
    const float* dw_w   = (const float*)d_in[21];
    const float* dw_b   = (const float*)d_in[22];
    const float* fc2_w  = (const float*)d_in[23];
    const float* fc2_b  = (const float*)d_in[24];
    float* out = (float*)d_out;

    float *x2b, *b512;
    __half *t1h, *qshb, *qnhb, *klhb, *vlhb, *f1hb, *yh, *xph, *atth, *y2h, *kph, *vphh, *gbh, *wh;
    cudaGetSymbolAddress((void**)&x2b,  g_x2);
    cudaGetSymbolAddress((void**)&b512, g_b512);
    cudaGetSymbolAddress((void**)&t1h,  g_t1h);
    cudaGetSymbolAddress((void**)&qshb, g_qsh);
    cudaGetSymbolAddress((void**)&qnhb, g_qnh);
    cudaGetSymbolAddress((void**)&klhb, g_klh);
    cudaGetSymbolAddress((void**)&vlhb, g_vlh);
    cudaGetSymbolAddress((void**)&f1hb, g_f1h);
    cudaGetSymbolAddress((void**)&yh,   g_yh);
    cudaGetSymbolAddress((void**)&xph,  g_xph);
    cudaGetSymbolAddress((void**)&atth, g_atth);
    cudaGetSymbolAddress((void**)&y2h,  g_y2h);
    cudaGetSymbolAddress((void**)&kph,  g_kph);
    cudaGetSymbolAddress((void**)&vphh, g_vph);
    cudaGetSymbolAddress((void**)&gbh,  g_gbh);
    cudaGetSymbolAddress((void**)&wh,   g_wh);

    cvt_all<<<840, 256>>>(q_w, kv_w, sr_w, proj_w, fc1_w, fc2_w, q_b, kv_b, sr_b, wh, b512);

    ln_kernel<<<TOK/8, 256>>>(x, n1w, n1b, yh);
    hgemm2<<<dim3(8,98), 128>>>(yh, wh+OQ, 128, b512, (float*)t1h, 512, 512, 3, nullptr);
    pointwise1<<<TOK/8, 256>>>(t1h, temp, qe, plnw, plnb, qshb, qnhb, klhb, vlhb, xph);
    hgemm_kv<<<dim3(4,98), 128>>>(xph, wh+OKV, kv_b, kph, vphh);
    attn_pool_mma<<<dim3(25,8), 256>>>(qshb, kph, vphh, qnhb, klhb, vlhb, lt, lb, atth);
    hgemm2<<<dim3(2,98), 128>>>(atth, wh+OPJ, 128, proj_b, x2b, 128, 128, 1, x);
    ln_kernel<<<TOK/8, 256>>>(x2b, n2w, n2b, y2h);
    hgemm2<<<dim3(11,98), 128>>>(y2h, wh+OF1, 128, fc1_b, (float*)f1hb, 682, 682, 3, nullptr);
    dwconv_kernel<<<TOK, LDF>>>(f1hb, dw_w, dw_b, gbh);
    hgemm2<<<dim3(2,98), 128>>>(gbh, wh+OF2, LDF, fc2_b, out, 128, 128, 2, x2b);
}

// round 16
// speedup vs baseline: 1.2064x; 1.1472x over previous
#include <cuda_runtime.h>
#include <cuda_fp16.h>
#include <math.h>

#define Bn   2
#define Cn   128
#define Hs   56
#define Nn   3136
#define NHn  4
#define HFn  341
#define TOK  (Bn*Nn)
#define LDF  352
#define LOG2E 1.4426950408889634f

// fp32 scratch
__device__ __align__(256) float g_x2 [TOK*Cn];
__device__ __align__(256) float g_b512[512];
// half scratch
__device__ __align__(256) __half g_t1h[TOK*512];
__device__ __align__(256) __half g_qsh[8*Nn*32];
__device__ __align__(256) __half g_qnh[8*Nn*32];
__device__ __align__(256) __half g_klh[8*Nn*32];
__device__ __align__(256) __half g_vlh[8*Nn*32];
__device__ __align__(256) __half g_f1h[TOK*682];
__device__ __align__(256) __half g_yh [TOK*Cn];
__device__ __align__(256) __half g_xph[TOK*Cn];
__device__ __align__(256) __half g_atth[TOK*Cn];
__device__ __align__(256) __half g_y2h[TOK*Cn];
__device__ __align__(256) __half g_kph[TOK*Cn];
__device__ __align__(256) __half g_vph[TOK*Cn];
__device__ __align__(256) __half g_gbh[TOK*LDF];
// converted weights pool (hi only)
#define OQ   0
#define OKV  16384
#define OSR  49152
#define OPJ  65536
#define OF1  81920
#define OF2  169216
#define WTOT 214272
__device__ __align__(256) __half g_wh[WTOT];

__device__ __forceinline__ float gelu_exact(float x) {
    return 0.5f * x * (1.0f + erff(x * 0.70710678118654752f));
}
__device__ __forceinline__ unsigned h2pack(float a, float b) {
    __half2 h = __floats2half2_rn(a, b);
    return *(unsigned*)&h;
}
__device__ __forceinline__ unsigned ex2_h2(unsigned x) {
    unsigned d;
    asm("ex2.approx.f16x2 %0, %1;" : "=r"(d) : "r"(x));
    return d;
}
__device__ __forceinline__ void mma16816(float* c, const unsigned* a, unsigned b0, unsigned b1) {
    asm volatile("mma.sync.aligned.m16n8k16.row.col.f32.f16.f16.f32 "
        "{%0,%1,%2,%3}, {%4,%5,%6,%7}, {%8,%9}, {%0,%1,%2,%3};"
        : "+f"(c[0]), "+f"(c[1]), "+f"(c[2]), "+f"(c[3])
        : "r"(a[0]), "r"(a[1]), "r"(a[2]), "r"(a[3]), "r"(b0), "r"(b1));
}
__device__ __forceinline__ unsigned smem_u32(const void* p) {
    unsigned a;
    asm("{ .reg .u64 t; cvta.to.shared.u64 t, %1; cvt.u32.u64 %0, t; }" : "=r"(a) : "l"(p));
    return a;
}
#define LDSM_X4(r0,r1,r2,r3,a) \
    asm volatile("ldmatrix.sync.aligned.m8n8.x4.shared.b16 {%0,%1,%2,%3}, [%4];" \
        : "=r"(r0),"=r"(r1),"=r"(r2),"=r"(r3) : "r"(a))
#define LDSM_X4T(r0,r1,r2,r3,a) \
    asm volatile("ldmatrix.sync.aligned.m8n8.x4.trans.shared.b16 {%0,%1,%2,%3}, [%4];" \
        : "=r"(r0),"=r"(r1),"=r"(r2),"=r"(r3) : "r"(a))
#define LDSM_X2T(r0,r1,a) \
    asm volatile("ldmatrix.sync.aligned.m8n8.x2.trans.shared.b16 {%0,%1}, [%2];" \
        : "=r"(r0),"=r"(r1) : "r"(a))

// ---------- single-launch weight conversion (hi only) + fused bias ----------
__global__ void cvt_all(const float* __restrict__ q_w, const float* __restrict__ kv_w,
                        const float* __restrict__ sr_w, const float* __restrict__ proj_w,
                        const float* __restrict__ fc1_w, const float* __restrict__ fc2_w,
                        const float* __restrict__ q_b, const float* __restrict__ kv_b,
                        const float* __restrict__ sr_b,
                        __half* __restrict__ wh, float* __restrict__ b512)
{
    int i = blockIdx.x * 256 + threadIdx.x;
    if (i < WTOT) {
        float v;
        if      (i < OKV) v = q_w[i];
        else if (i < OSR) v = kv_w[i - OKV];
        else if (i < OPJ) v = sr_w[i - OSR];
        else if (i < OF1) v = proj_w[i - OPJ];
        else if (i < OF2) v = fc1_w[i - OF1];
        else {
            int j = i - OF2, r = j / LDF, c = j - r * LDF;
            v = (c < HFn) ? fc2_w[r * HFn + c] : 0.f;
        }
        wh[i] = __float2half_rn(v);
    } else if (i < WTOT + 512) {
        int j = i - WTOT;
        b512[j] = (j < 128) ? q_b[j] : (j < 384) ? kv_b[j - 128] : sr_b[j - 384];
    }
}

// ---------- LayerNorm (channel-major in) -> fp16 token-major ----------
__global__ void ln_kernel(const float* __restrict__ in, const float* __restrict__ w,
                          const float* __restrict__ bvec, __half* __restrict__ oh)
{
    int warp = blockIdx.x * 8 + (threadIdx.x >> 5);
    int lane = threadIdx.x & 31;
    int bb = warp / Nn, n = warp - bb * Nn;
    const float* p = in + (size_t)bb * (Cn*Nn) + n;
    float v[4], s = 0.f, s2 = 0.f;
#pragma unroll
    for (int pp = 0; pp < 2; pp++) {
        int c0 = 2*lane + 64*pp;
        v[2*pp]   = p[(size_t)c0 * Nn];
        v[2*pp+1] = p[(size_t)(c0+1) * Nn];
        s += v[2*pp] + v[2*pp+1];
        s2 += v[2*pp]*v[2*pp] + v[2*pp+1]*v[2*pp+1];
    }
#pragma unroll
    for (int d = 1; d < 32; d <<= 1) {
        s  += __shfl_xor_sync(0xffffffffu, s,  d);
        s2 += __shfl_xor_sync(0xffffffffu, s2, d);
    }
    float mu = s * (1.0f/128.0f);
    float rstd = rsqrtf(s2*(1.0f/128.0f) - mu*mu + 1e-5f);
    unsigned* ohp = (unsigned*)oh;
#pragma unroll
    for (int pp = 0; pp < 2; pp++) {
        int c0 = 2*lane + 64*pp;
        float a = (v[2*pp]  -mu)*rstd*w[c0]   + bvec[c0];
        float b = (v[2*pp+1]-mu)*rstd*w[c0+1] + bvec[c0+1];
        ohp[warp*64 + lane + 32*pp] = h2pack(a, b);
    }
}

// ---------- HMMA GEMM: single fp16 A x W ----------
__global__ void __launch_bounds__(128) hgemm2(
    const __half* __restrict__ Ah, const __half* __restrict__ Wh, int ld,
    const float* __restrict__ bias, float* __restrict__ out,
    int ldo, int Nout, int mode, const float* __restrict__ res)
{
    const int m0 = blockIdx.y * 64;
    const int n0 = blockIdx.x * 64;
    const int warp = threadIdx.x >> 5;
    const int lane = threadIdx.x & 31;
    const int r  = lane >> 2;
    const int c2 = (lane & 3) * 2;

    float acc[8][4];
#pragma unroll
    for (int t = 0; t < 8; t++)
#pragma unroll
        for (int i = 0; i < 4; i++) acc[t][i] = 0.f;

    const int row1 = m0 + warp*16 + r;
    const __half* a1h = Ah + (size_t)row1 * ld;
    const __half* a2h = a1h + (size_t)8 * ld;

    const int nr = n0 + (lane >> 2);
    const __half* wrow[8];
#pragma unroll
    for (int nt = 0; nt < 8; nt++) {
        int n = nr + nt*8;
        int nc = (n < Nout) ? n : (Nout - 1);
        wrow[nt] = Wh + (size_t)nc * ld;
    }

    const int KC = ld / 32;
    for (int kc = 0; kc < KC; kc++) {
#pragma unroll
        for (int ks = 0; ks < 2; ks++) {
            int d0 = kc*32 + ks*16 + c2;
            unsigned ah[4];
            ah[0] = *(const unsigned*)&a1h[d0];
            ah[1] = *(const unsigned*)&a2h[d0];
            ah[2] = *(const unsigned*)&a1h[d0+8];
            ah[3] = *(const unsigned*)&a2h[d0+8];
#pragma unroll
            for (int nt = 0; nt < 8; nt++) {
                unsigned bh0 = *(const unsigned*)&wrow[nt][d0];
                unsigned bh1 = *(const unsigned*)&wrow[nt][d0+8];
                mma16816(acc[nt], ah, bh0, bh1);
            }
        }
    }

    int m1 = row1, m2 = row1 + 8;
#pragma unroll
    for (int nt = 0; nt < 8; nt++) {
        int n = n0 + nt*8 + c2;
#pragma unroll
        for (int j = 0; j < 2; j++) {
            int nn = n + j;
            if (nn >= Nout) continue;
            float v1 = acc[nt][j]   + bias[nn];
            float v2 = acc[nt][2+j] + bias[nn];
            if (mode == 0) {
                out[(size_t)m1*ldo + nn] = v1;
                out[(size_t)m2*ldo + nn] = v2;
            } else if (mode == 1) {
                size_t i1 = (size_t)m1*ldo + nn, i2 = (size_t)m2*ldo + nn;
                out[i1] = v1 + res[i1];
                out[i2] = v2 + res[i2];
            } else if (mode == 2) {
                int b1 = m1 / Nn, t1i = m1 - b1*Nn;
                int b2 = m2 / Nn, t2i = m2 - b2*Nn;
                size_t i1 = ((size_t)b1*Cn + nn)*Nn + t1i;
                size_t i2 = ((size_t)b2*Cn + nn)*Nn + t2i;
                out[i1] = v1 + res[i1];
                out[i2] = v2 + res[i2];
            } else {
                __half* oh = (__half*)out;
                oh[(size_t)m1*ldo + nn] = __float2half_rn(v1);
                oh[(size_t)m2*ldo + nn] = __float2half_rn(v2);
            }
        }
    }
}

// ---------- HMMA kv GEMM with fused l2norm/split epilogue -> kph/vph fp16 ----------
__global__ void __launch_bounds__(128) hgemm_kv(
    const __half* __restrict__ Ah, const __half* __restrict__ Wh,
    const float* __restrict__ bias,
    __half* __restrict__ kph, __half* __restrict__ vph)
{
    const int m0 = blockIdx.y * 64;
    const int n0 = blockIdx.x * 64;
    const int warp = threadIdx.x >> 5;
    const int lane = threadIdx.x & 31;
    const int r  = lane >> 2;
    const int c2 = (lane & 3) * 2;
    const int ld = 128;

    float acc[8][4];
#pragma unroll
    for (int t = 0; t < 8; t++)
#pragma unroll
        for (int i = 0; i < 4; i++) acc[t][i] = 0.f;

    const int row1 = m0 + warp*16 + r;
    const __half* a1h = Ah + (size_t)row1 * ld;
    const __half* a2h = a1h + (size_t)8 * ld;

    const int nr = n0 + (lane >> 2);
    const __half* wrow[8];
#pragma unroll
    for (int nt = 0; nt < 8; nt++)
        wrow[nt] = Wh + (size_t)(nr + nt*8) * ld;

#pragma unroll
    for (int kc = 0; kc < 4; kc++) {
#pragma unroll
        for (int ks = 0; ks < 2; ks++) {
            int d0 = kc*32 + ks*16 + c2;
            unsigned ah[4];
            ah[0] = *(const unsigned*)&a1h[d0];
            ah[1] = *(const unsigned*)&a2h[d0];
            ah[2] = *(const unsigned*)&a1h[d0+8];
            ah[3] = *(const unsigned*)&a2h[d0+8];
#pragma unroll
            for (int nt = 0; nt < 8; nt++) {
                unsigned bh0 = *(const unsigned*)&wrow[nt][d0];
                unsigned bh1 = *(const unsigned*)&wrow[nt][d0+8];
                mma16816(acc[nt], ah, bh0, bh1);
            }
        }
    }

#pragma unroll
    for (int half = 0; half < 2; half++) {
        int m = row1 + half*8;
        int bb = m / Nn, n = m - bb*Nn;
        float vals[16];
#pragma unroll
        for (int nt = 0; nt < 8; nt++)
#pragma unroll
            for (int j = 0; j < 2; j++)
                vals[nt*2+j] = acc[nt][half*2+j] + bias[n0 + nt*8 + c2 + j];
        if (n0 < 128) {
            float se = 0.f, so = 0.f;
#pragma unroll
            for (int i = 0; i < 8; i++) { se += vals[i]*vals[i]; so += vals[8+i]*vals[8+i]; }
            se += __shfl_xor_sync(0xffffffffu, se, 1);
            se += __shfl_xor_sync(0xffffffffu, se, 2);
            so += __shfl_xor_sync(0xffffffffu, so, 1);
            so += __shfl_xor_sync(0xffffffffu, so, 2);
            float ke = 1.0f / fmaxf(sqrtf(se), 1e-12f);
            float ko = 1.0f / fmaxf(sqrtf(so), 1e-12f);
#pragma unroll
            for (int nt = 0; nt < 8; nt++) {
                int col = n0 + nt*8 + c2;
                int head = col >> 5;
                float sc = (nt < 4) ? ke : ko;
                __half2 hv = __floats2half2_rn(vals[nt*2]*sc, vals[nt*2+1]*sc);
                *(__half2*)&kph[((size_t)(bb*NHn + head)*Nn + n)*32 + (col & 31)] = hv;
            }
        } else {
#pragma unroll
            for (int nt = 0; nt < 8; nt++) {
                int col = n0 - 128 + nt*8 + c2;
                int head = col >> 5;
                __half2 hv = __floats2half2_rn(vals[nt*2], vals[nt*2+1]);
                *(__half2*)&vph[((size_t)(bb*NHn + head)*Nn + n)*32 + (col & 31)] = hv;
            }
        }
    }
}

// ---------- pointwise after fused QKVSR GEMM (qs pre-scaled by log2e) ----------
__global__ void pointwise1(const __half* __restrict__ t1h, const float* __restrict__ temp,
                           const float* __restrict__ qe, const float* __restrict__ plnw,
                           const float* __restrict__ plnb,
                           __half* __restrict__ qsh, __half* __restrict__ qnh,
                           __half* __restrict__ klh, __half* __restrict__ vlh,
                           __half* __restrict__ xph)
{
    int t = blockIdx.x * 8 + (threadIdx.x >> 5);
    int lane = threadIdx.x & 31;
    int bb = t / Nn, n = t - bb * Nn;
    int h = lane >> 3;
    int g = bb * NHn + h;
    const __half2* row = (const __half2*)(t1h + (size_t)t * 512);
    unsigned base = ((unsigned)g*Nn + n)*16 + (lane & 7)*2;

    __half2 qa = row[2*lane], qb = row[2*lane + 1];
    float q0 = __half2float(qa.x), q1 = __half2float(qa.y);
    float q2 = __half2float(qb.x), q3 = __half2float(qb.y);
    float ss = q0*q0 + q1*q1 + q2*q2 + q3*q3;
    ss += __shfl_xor_sync(0xffffffffu, ss, 1);
    ss += __shfl_xor_sync(0xffffffffu, ss, 2);
    ss += __shfl_xor_sync(0xffffffffu, ss, 4);
    float inv = 1.0f / fmaxf(sqrtf(ss), 1e-12f);
    float n0 = q0*inv, n1 = q1*inv, n2 = q2*inv, n3 = q3*inv;
    float tv = temp[h];
    float sp = log1pf(__expf(tv)) * LOG2E;
    float4 qe4 = ((const float4*)qe)[h*8 + (lane & 7)];
    ((unsigned*)qnh)[base]   = h2pack(n0, n1);
    ((unsigned*)qnh)[base+1] = h2pack(n2, n3);
    ((unsigned*)qsh)[base]   = h2pack((n0+qe4.x)*sp, (n1+qe4.y)*sp);
    ((unsigned*)qsh)[base+1] = h2pack((n2+qe4.z)*sp, (n3+qe4.w)*sp);

    __half2 ka = row[64 + 2*lane], kb = row[64 + 2*lane + 1];
    float k0 = __half2float(ka.x), k1 = __half2float(ka.y);
    float k2 = __half2float(kb.x), k3 = __half2float(kb.y);
    float ks = k0*k0 + k1*k1 + k2*k2 + k3*k3;
    ks += __shfl_xor_sync(0xffffffffu, ks, 1);
    ks += __shfl_xor_sync(0xffffffffu, ks, 2);
    ks += __shfl_xor_sync(0xffffffffu, ks, 4);
    float ki = 1.0f / fmaxf(sqrtf(ks), 1e-12f);
    ((unsigned*)klh)[base]   = h2pack(k0*ki, k1*ki);
    ((unsigned*)klh)[base+1] = h2pack(k2*ki, k3*ki);

    ((unsigned*)vlh)[base]   = *(const unsigned*)&row[128 + 2*lane];
    ((unsigned*)vlh)[base+1] = *(const unsigned*)&row[128 + 2*lane + 1];

    __half2 sa = row[192 + 2*lane], sb = row[192 + 2*lane + 1];
    float g0 = gelu_exact(__half2float(sa.x)), g1 = gelu_exact(__half2float(sa.y));
    float g2 = gelu_exact(__half2float(sb.x)), g3 = gelu_exact(__half2float(sb.y));
    float sm = g0+g1+g2+g3;
    float sq = g0*g0+g1*g1+g2*g2+g3*g3;
#pragma unroll
    for (int d = 1; d < 32; d <<= 1) {
        sm += __shfl_xor_sync(0xffffffffu, sm, d);
        sq += __shfl_xor_sync(0xffffffffu, sq, d);
    }
    float mu = sm*(1.0f/128.0f);
    float rstd = rsqrtf(sq*(1.0f/128.0f) - mu*mu + 1e-5f);
    int c = lane * 4;
    float o0 = (g0-mu)*rstd*plnw[c]   + plnb[c];
    float o1 = (g1-mu)*rstd*plnw[c+1] + plnb[c+1];
    float o2 = (g2-mu)*rstd*plnw[c+2] + plnb[c+2];
    float o3 = (g3-mu)*rstd*plnw[c+3] + plnb[c+3];
    unsigned* xh = (unsigned*)xph;
    xh[(size_t)t*64 + lane*2]     = h2pack(o0, o1);
    xh[(size_t)t*64 + lane*2 + 1] = h2pack(o2, o3);
}

// ---------- HMMA pooled attention: ldmatrix fragments + ex2.f16x2 + Z-column ----------
__global__ void __launch_bounds__(256) attn_pool_mma(
    const __half* __restrict__ qsh, const __half* __restrict__ kph,
    const __half* __restrict__ vph,
    const __half* __restrict__ qnh, const __half* __restrict__ klh,
    const __half* __restrict__ vlh, const float* __restrict__ lt,
    const float* __restrict__ lb,
    __half* __restrict__ atth)
{
    __shared__ __half Khi[128][40];
    __shared__ __half Vr[128][40];   // row-major V; col 32 = valid mask, 33-39 = 0

    const int g  = blockIdx.y;
    const int tid = threadIdx.x;
    const int warp = tid >> 5;
    const int lane = tid & 31;
    const int r  = lane >> 2;
    const int c2 = (lane & 3) * 2;
    const int qbase = blockIdx.x * 128 + (warp >> 2) * 64 + (warp & 3) * 16 + r;
    const int qrow_l = (qbase < Nn) ? qbase : (Nn - 1);

    // ldmatrix per-lane base addresses (bytes)
    const unsigned sK = smem_u32(Khi);
    const unsigned sV = smem_u32(Vr);
    const int l7 = lane & 7;
    // QK (non-trans): lanes 0-7: tile kv 0-7 col 0 | 8-15: kv 0-7 col 8 | 16-23: kv 8-15 col 0 | 24-31: kv 8-15 col 8
    const unsigned qk_base = sK + (unsigned)((l7 + ((lane >> 4) << 3)) * 80 + ((lane >> 3) & 1) * 16);
    // EV (trans): lanes 0-7: kv 0-7 d0 | 8-15: kv 8-15 d0 | 16-23: kv 0-7 d8 | 24-31: kv 8-15 d8
    const unsigned ev_base = sV + (unsigned)((l7 + ((lane >> 3) & 1) * 8) * 80 + ((lane >> 4) & 1) * 16);
    // EV tail (x2.trans, lanes 0-15): kv 0-7 / 8-15 at d=32
    const unsigned evt_base = sV + (unsigned)((l7 + ((lane >> 3) & 1) * 8) * 80 + 64);

    unsigned qhi[2][4];
    {
        const __half* q0p = qsh + ((size_t)g*Nn + qrow_l)*32;
        int q8c = (qbase + 8 < Nn) ? (qbase + 8) : (Nn - 1);
        const __half* q8p = qsh + ((size_t)g*Nn + q8c)*32;
#pragma unroll
        for (int ks = 0; ks < 2; ks++) {
            int d0 = ks*16 + c2;
            qhi[ks][0] = *(const unsigned*)&q0p[d0];
            qhi[ks][1] = *(const unsigned*)&q8p[d0];
            qhi[ks][2] = *(const unsigned*)&q0p[d0+8];
            qhi[ks][3] = *(const unsigned*)&q8p[d0+8];
        }
    }

    float uf[5][4];
#pragma unroll
    for (int t = 0; t < 5; t++)
#pragma unroll
        for (int i = 0; i < 4; i++) uf[t][i] = 0.f;

    const int NCH = 25;
    for (int ch = 0; ch < NCH; ch++) {
        const int m0 = ch * 128;
        {
            int row = tid & 127;
            int hp  = tid >> 7;
            int kvr = m0 + row;
            bool ok = kvr < Nn;
            size_t rb = ((size_t)g*Nn + (ok ? kvr : 0))*32;
            const uint4* krh = (const uint4*)(kph + rb);
            const uint4* vr4 = (const uint4*)(vph + rb);
            uint4 z4 = make_uint4(0,0,0,0);
#pragma unroll
            for (int j = 0; j < 2; j++) {
                *(uint4*)&Khi[row][(hp*2 + j)*8] = ok ? krh[hp*2 + j] : z4;
                *(uint4*)&Vr[row][(hp*2 + j)*8]  = ok ? vr4[hp*2 + j] : z4;
            }
            if (hp) {
                uint4 m4 = make_uint4(ok ? 0x00003C00u : 0u, 0u, 0u, 0u);
                *(uint4*)&Vr[row][32] = m4;
            }
        }
        __syncthreads();

        const int kkmax = (m0 + 128 <= Nn) ? 8 : 4;
        for (int kk = 0; kk < kkmax; kk++) {
            const unsigned qka = qk_base + kk*1280;
            float s0[4] = {0.f,0.f,0.f,0.f};
            float s1[4] = {0.f,0.f,0.f,0.f};
#pragma unroll
            for (int ks = 0; ks < 2; ks++) {
                unsigned b00, b01, b10, b11;
                LDSM_X4(b00, b01, b10, b11, qka + ks*32);
                mma16816(s0, qhi[ks], b00, b01);
                mma16816(s1, qhi[ks], b10, b11);
            }
            unsigned ea[4];
            ea[0] = ex2_h2(h2pack(s0[0], s0[1]));
            ea[1] = ex2_h2(h2pack(s0[2], s0[3]));
            ea[2] = ex2_h2(h2pack(s1[0], s1[1]));
            ea[3] = ex2_h2(h2pack(s1[2], s1[3]));

            const unsigned eva = ev_base + kk*1280;
#pragma unroll
            for (int ntp = 0; ntp < 2; ntp++) {
                unsigned v0, v1, v2, v3;
                LDSM_X4T(v0, v1, v2, v3, eva + ntp*32);
                mma16816(uf[2*ntp],     ea, v0, v1);
                mma16816(uf[2*ntp + 1], ea, v2, v3);
            }
            unsigned t0, t1;
            LDSM_X2T(t0, t1, evt_base + kk*1280);
            mma16816(uf[4], ea, t0, t1);
        }
        __syncthreads();
    }

    // Z sits at col 32 (uf[4], tile col 0) held by quad-base lane
    float z0 = __shfl_sync(0xffffffffu, uf[4][0], lane & 28);
    float z1 = __shfl_sync(0xffffffffu, uf[4][2], lane & 28);

    const int b = g >> 2, h = g & 3;
#pragma unroll
    for (int half = 0; half < 2; half++) {
        int n = qbase + half*8;
        bool nok = n < Nn;
        int nc = nok ? n : (Nn - 1);
        float Zpool = half ? z1 : z0;
        int hh = nc / Hs, ww = nc - hh*Hs;
        const __half* qp  = qsh + ((size_t)g*Nn + nc)*32;
        const __half* qnp = qnh + ((size_t)g*Nn + nc)*32;
        float qsv[8], qnv[8];
#pragma unroll
        for (int nt = 0; nt < 4; nt++) {
            int c = nt*8 + c2;
            __half2 a = *(const __half2*)&qp[c];
            __half2 bq = *(const __half2*)&qnp[c];
            qsv[nt*2]   = __half2float(a.x);  qsv[nt*2+1] = __half2float(a.y);
            qnv[nt*2]   = __half2float(bq.x); qnv[nt*2+1] = __half2float(bq.y);
        }
        float resv[8], res2v[8];
#pragma unroll
        for (int i = 0; i < 8; i++) { resv[i] = 0.f; res2v[i] = 0.f; }
        float zl = 0.f;
#pragma unroll
        for (int k = 0; k < 9; k++) {
            int h2 = hh + k/3 - 1, w2 = ww + (k%3) - 1;
            bool ok = (h2 >= 0 && h2 < Hs && w2 >= 0 && w2 < Hs);
            size_t bi = ((size_t)g*Nn + (ok ? (h2*Hs + w2) : 0))*32;
            float klv[8], vlv[8];
            float lg = 0.f, wl = 0.f;
#pragma unroll
            for (int nt = 0; nt < 4; nt++) {
                int c = nt*8 + c2;
                __half2 kk2 = ok ? *(const __half2*)&klh[bi + c] : __half2(__float2half(0.f), __float2half(0.f));
                __half2 vv2 = ok ? *(const __half2*)&vlh[bi + c] : __half2(__float2half(0.f), __float2half(0.f));
                int idx = nt*2;
                klv[idx]   = __half2float(kk2.x); klv[idx+1] = __half2float(kk2.y);
                vlv[idx]   = __half2float(vv2.x); vlv[idx+1] = __half2float(vv2.y);
                lg += qsv[idx]*klv[idx] + qsv[idx+1]*klv[idx+1];
                wl += qnv[idx]*lt[(h*32 + c)*9 + k] + qnv[idx+1]*lt[(h*32 + c + 1)*9 + k];
            }
            lg += __shfl_xor_sync(0xffffffffu, lg, 1);
            lg += __shfl_xor_sync(0xffffffffu, lg, 2);
            wl += __shfl_xor_sync(0xffffffffu, wl, 1);
            wl += __shfl_xor_sync(0xffffffffu, wl, 2);
            float e = exp2f(lg);
            zl += e;
            float w2l = wl + lb[h*9 + k];
#pragma unroll
            for (int i = 0; i < 8; i++) {
                resv[i]  += e   * vlv[i];
                res2v[i] += w2l * vlv[i];
            }
        }
        float Zf = Zpool + zl;
        float rZ = 1.0f / Zf;
        if (nok) {
#pragma unroll
            for (int nt = 0; nt < 4; nt++)
#pragma unroll
                for (int j = 0; j < 2; j++) {
                    int c = nt*8 + c2 + j;
                    int idx = nt*2 + j;
                    float o = (uf[nt][half*2 + j] + resv[idx]) * rZ + res2v[idx];
                    size_t oi = ((size_t)(b*Nn + n))*128 + h*32 + c;
                    atth[oi] = __float2half_rn(o);
                }
        }
    }
}

// ---------- depthwise 3x3 + gelu * v: 2 adjacent tokens per thread ----------
__global__ void __launch_bounds__(LDF) dwconv_kernel(
    const __half* __restrict__ f1, const float* __restrict__ dww,
    const float* __restrict__ dwb, __half* __restrict__ gbh)
{
    int t0 = blockIdx.x * 2;
    int c = threadIdx.x;
    size_t o0 = (size_t)t0*LDF + c, o1 = o0 + LDF;
    if (c >= HFn) {
        gbh[o0] = __float2half(0.f);
        gbh[o1] = __float2half(0.f);
        return;
    }
    int b = t0 / Nn, n = t0 - b*Nn;
    int hh = n / Hs, ww = n - hh*Hs;   // ww even, ww+1 valid
    float w[9];
#pragma unroll
    for (int k = 0; k < 9; k++) w[k] = dww[c*9 + k];
    float acc0 = dwb[c], acc1 = acc0;
#pragma unroll
    for (int dr = -1; dr <= 1; dr++) {
        int h2 = hh + dr;
        if (h2 < 0 || h2 >= Hs) continue;
#pragma unroll
        for (int dc = -1; dc <= 2; dc++) {
            int w2 = ww + dc;
            if (w2 < 0 || w2 >= Hs) continue;
            float v = __half2float(f1[((size_t)(b*Nn + h2*Hs + w2))*682 + c]);
            if (dc <= 1) acc0 += v * w[(dr+1)*3 + dc + 1];
            if (dc >= 0) acc1 += v * w[(dr+1)*3 + dc];
        }
    }
    float v0 = __half2float(f1[(size_t)t0*682 + 341 + c]);
    float v1 = __half2float(f1[(size_t)(t0+1)*682 + 341 + c]);
    gbh[o0] = __float2half_rn(gelu_exact(acc0) * v0);
    gbh[o1] = __float2half_rn(gelu_exact(acc1) * v1);
}

extern "C" void kernel_launch(void* const* d_in, const int* in_sizes, int n_in,
                              void* d_out, int out_size)
{
    const float* x      = (const float*)d_in[0];
    const float* n1w    = (const float*)d_in[1];
    const float* n1b    = (const float*)d_in[2];
    const float* q_w    = (const float*)d_in[3];
    const float* q_b    = (const float*)d_in[4];
    const float* kv_w   = (const float*)d_in[5];
    const float* kv_b   = (const float*)d_in[6];
    const float* temp   = (const float*)d_in[7];
    const float* qe     = (const float*)d_in[8];
    const float* lt     = (const float*)d_in[9];
    const float* lb     = (const float*)d_in[10];
    const float* sr_w   = (const float*)d_in[11];
    const float* sr_b   = (const float*)d_in[12];
    const float* plnw   = (const float*)d_in[13];
    const float* plnb   = (const float*)d_in[14];
    const float* proj_w = (const float*)d_in[15];
    const float* proj_b = (const float*)d_in[16];
    const float* n2w    = (const float*)d_in[17];
    const float* n2b    = (const float*)d_in[18];
    const float* fc1_w  = (const float*)d_in[19];
    const float* fc1_b  = (const float*)d_in[20];
    const float* dw_w   = (const float*)d_in[21];
    const float* dw_b   = (const float*)d_in[22];
    const float* fc2_w  = (const float*)d_in[23];
    const float* fc2_b  = (const float*)d_in[24];
    float* out = (float*)d_out;

    float *x2b, *b512;
    __half *t1h, *qshb, *qnhb, *klhb, *vlhb, *f1hb, *yh, *xph, *atth, *y2h, *kph, *vphh, *gbh, *wh;
    cudaGetSymbolAddress((void**)&x2b,  g_x2);
    cudaGetSymbolAddress((void**)&b512, g_b512);
    cudaGetSymbolAddress((void**)&t1h,  g_t1h);
    cudaGetSymbolAddress((void**)&qshb, g_qsh);
    cudaGetSymbolAddress((void**)&qnhb, g_qnh);
    cudaGetSymbolAddress((void**)&klhb, g_klh);
    cudaGetSymbolAddress((void**)&vlhb, g_vlh);
    cudaGetSymbolAddress((void**)&f1hb, g_f1h);
    cudaGetSymbolAddress((void**)&yh,   g_yh);
    cudaGetSymbolAddress((void**)&xph,  g_xph);
    cudaGetSymbolAddress((void**)&atth, g_atth);
    cudaGetSymbolAddress((void**)&y2h,  g_y2h);
    cudaGetSymbolAddress((void**)&kph,  g_kph);
    cudaGetSymbolAddress((void**)&vphh, g_vph);
    cudaGetSymbolAddress((void**)&gbh,  g_gbh);
    cudaGetSymbolAddress((void**)&wh,   g_wh);

    cvt_all<<<840, 256>>>(q_w, kv_w, sr_w, proj_w, fc1_w, fc2_w, q_b, kv_b, sr_b, wh, b512);

    ln_kernel<<<TOK/8, 256>>>(x, n1w, n1b, yh);
    hgemm2<<<dim3(8,98), 128>>>(yh, wh+OQ, 128, b512, (float*)t1h, 512, 512, 3, nullptr);
    pointwise1<<<TOK/8, 256>>>(t1h, temp, qe, plnw, plnb, qshb, qnhb, klhb, vlhb, xph);
    hgemm_kv<<<dim3(4,98), 128>>>(xph, wh+OKV, kv_b, kph, vphh);
    attn_pool_mma<<<dim3(25,8), 256>>>(qshb, kph, vphh, qnhb, klhb, vlhb, lt, lb, atth);
    hgemm2<<<dim3(2,98), 128>>>(atth, wh+OPJ, 128, proj_b, x2b, 128, 128, 1, x);
    ln_kernel<<<TOK/8, 256>>>(x2b, n2w, n2b, y2h);
    hgemm2<<<dim3(11,98), 128>>>(y2h, wh+OF1, 128, fc1_b, (float*)f1hb, 682, 682, 3, nullptr);
    dwconv_kernel<<<TOK/2, LDF>>>(f1hb, dw_w, dw_b, gbh);
    hgemm2<<<dim3(2,98), 128>>>(gbh, wh+OF2, LDF, fc2_b, out, 128, 128, 2, x2b);
}

// round 17
// speedup vs baseline: 1.2527x; 1.0384x over previous
#include <cuda_runtime.h>
#include <cuda_fp16.h>
#include <math.h>

#define Bn   2
#define Cn   128
#define Hs   56
#define Nn   3136
#define NHn  4
#define HFn  341
#define TOK  (Bn*Nn)
#define LDF  352
#define LOG2E 1.4426950408889634f

// fp32 scratch
__device__ __align__(256) float g_x2 [TOK*Cn];
__device__ __align__(256) float g_b512[512];
// half scratch
__device__ __align__(256) __half g_t1h[TOK*512];
__device__ __align__(256) __half g_qsh[8*Nn*32];
__device__ __align__(256) __half g_qnh[8*Nn*32];
__device__ __align__(256) __half g_klh[8*Nn*32];
__device__ __align__(256) __half g_vlh[8*Nn*32];
__device__ __align__(256) __half g_f1h[TOK*682];
__device__ __align__(256) __half g_yh [TOK*Cn];
__device__ __align__(256) __half g_xph[TOK*Cn];
__device__ __align__(256) __half g_atth[TOK*Cn];
__device__ __align__(256) __half g_y2h[TOK*Cn];
__device__ __align__(256) __half g_kph[TOK*Cn];
__device__ __align__(256) __half g_vph[TOK*Cn];
__device__ __align__(256) __half g_gbh[TOK*LDF];
// converted weights pool (hi only)
#define OQ   0
#define OKV  16384
#define OSR  49152
#define OPJ  65536
#define OF1  81920
#define OF2  169216
#define WTOT 214272
__device__ __align__(256) __half g_wh[WTOT];

__device__ __forceinline__ float gelu_exact(float x) {
    return 0.5f * x * (1.0f + erff(x * 0.70710678118654752f));
}
__device__ __forceinline__ unsigned h2pack(float a, float b) {
    __half2 h = __floats2half2_rn(a, b);
    return *(unsigned*)&h;
}
__device__ __forceinline__ unsigned ex2_h2(unsigned x) {
    unsigned d;
    asm("ex2.approx.f16x2 %0, %1;" : "=r"(d) : "r"(x));
    return d;
}
__device__ __forceinline__ void mma16816(float* c, const unsigned* a, unsigned b0, unsigned b1) {
    asm volatile("mma.sync.aligned.m16n8k16.row.col.f32.f16.f16.f32 "
        "{%0,%1,%2,%3}, {%4,%5,%6,%7}, {%8,%9}, {%0,%1,%2,%3};"
        : "+f"(c[0]), "+f"(c[1]), "+f"(c[2]), "+f"(c[3])
        : "r"(a[0]), "r"(a[1]), "r"(a[2]), "r"(a[3]), "r"(b0), "r"(b1));
}
__device__ __forceinline__ unsigned smem_u32(const void* p) {
    unsigned a;
    asm("{ .reg .u64 t; cvta.to.shared.u64 t, %1; cvt.u32.u64 %0, t; }" : "=r"(a) : "l"(p));
    return a;
}
#define LDSM_X4(r0,r1,r2,r3,a) \
    asm volatile("ldmatrix.sync.aligned.m8n8.x4.shared.b16 {%0,%1,%2,%3}, [%4];" \
        : "=r"(r0),"=r"(r1),"=r"(r2),"=r"(r3) : "r"(a))
#define LDSM_X4T(r0,r1,r2,r3,a) \
    asm volatile("ldmatrix.sync.aligned.m8n8.x4.trans.shared.b16 {%0,%1,%2,%3}, [%4];" \
        : "=r"(r0),"=r"(r1),"=r"(r2),"=r"(r3) : "r"(a))
#define LDSM_X2T(r0,r1,a) \
    asm volatile("ldmatrix.sync.aligned.m8n8.x2.trans.shared.b16 {%0,%1}, [%2];" \
        : "=r"(r0),"=r"(r1) : "r"(a))

// ---------- single-launch weight conversion (hi only) + fused bias ----------
__global__ void cvt_all(const float* __restrict__ q_w, const float* __restrict__ kv_w,
                        const float* __restrict__ sr_w, const float* __restrict__ proj_w,
                        const float* __restrict__ fc1_w, const float* __restrict__ fc2_w,
                        const float* __restrict__ q_b, const float* __restrict__ kv_b,
                        const float* __restrict__ sr_b,
                        __half* __restrict__ wh, float* __restrict__ b512)
{
    int i = blockIdx.x * 256 + threadIdx.x;
    if (i < WTOT) {
        float v;
        if      (i < OKV) v = q_w[i];
        else if (i < OSR) v = kv_w[i - OKV];
        else if (i < OPJ) v = sr_w[i - OSR];
        else if (i < OF1) v = proj_w[i - OPJ];
        else if (i < OF2) v = fc1_w[i - OF1];
        else {
            int j = i - OF2, r = j / LDF, c = j - r * LDF;
            v = (c < HFn) ? fc2_w[r * HFn + c] : 0.f;
        }
        wh[i] = __float2half_rn(v);
    } else if (i < WTOT + 512) {
        int j = i - WTOT;
        b512[j] = (j < 128) ? q_b[j] : (j < 384) ? kv_b[j - 128] : sr_b[j - 384];
    }
}

// ---------- LayerNorm (channel-major in) -> fp16 token-major ----------
__global__ void ln_kernel(const float* __restrict__ in, const float* __restrict__ w,
                          const float* __restrict__ bvec, __half* __restrict__ oh)
{
    int warp = blockIdx.x * 8 + (threadIdx.x >> 5);
    int lane = threadIdx.x & 31;
    int bb = warp / Nn, n = warp - bb * Nn;
    const float* p = in + (size_t)bb * (Cn*Nn) + n;
    float v[4], s = 0.f, s2 = 0.f;
#pragma unroll
    for (int pp = 0; pp < 2; pp++) {
        int c0 = 2*lane + 64*pp;
        v[2*pp]   = p[(size_t)c0 * Nn];
        v[2*pp+1] = p[(size_t)(c0+1) * Nn];
        s += v[2*pp] + v[2*pp+1];
        s2 += v[2*pp]*v[2*pp] + v[2*pp+1]*v[2*pp+1];
    }
#pragma unroll
    for (int d = 1; d < 32; d <<= 1) {
        s  += __shfl_xor_sync(0xffffffffu, s,  d);
        s2 += __shfl_xor_sync(0xffffffffu, s2, d);
    }
    float mu = s * (1.0f/128.0f);
    float rstd = rsqrtf(s2*(1.0f/128.0f) - mu*mu + 1e-5f);
    unsigned* ohp = (unsigned*)oh;
#pragma unroll
    for (int pp = 0; pp < 2; pp++) {
        int c0 = 2*lane + 64*pp;
        float a = (v[2*pp]  -mu)*rstd*w[c0]   + bvec[c0];
        float b = (v[2*pp+1]-mu)*rstd*w[c0+1] + bvec[c0+1];
        ohp[warp*64 + lane + 32*pp] = h2pack(a, b);
    }
}

// ---------- HMMA GEMM: single fp16 A x W ----------
__global__ void __launch_bounds__(128) hgemm2(
    const __half* __restrict__ Ah, const __half* __restrict__ Wh, int ld,
    const float* __restrict__ bias, float* __restrict__ out,
    int ldo, int Nout, int mode, const float* __restrict__ res)
{
    const int m0 = blockIdx.y * 64;
    const int n0 = blockIdx.x * 64;
    const int warp = threadIdx.x >> 5;
    const int lane = threadIdx.x & 31;
    const int r  = lane >> 2;
    const int c2 = (lane & 3) * 2;

    float acc[8][4];
#pragma unroll
    for (int t = 0; t < 8; t++)
#pragma unroll
        for (int i = 0; i < 4; i++) acc[t][i] = 0.f;

    const int row1 = m0 + warp*16 + r;
    const __half* a1h = Ah + (size_t)row1 * ld;
    const __half* a2h = a1h + (size_t)8 * ld;

    const int nr = n0 + (lane >> 2);
    const __half* wrow[8];
#pragma unroll
    for (int nt = 0; nt < 8; nt++) {
        int n = nr + nt*8;
        int nc = (n < Nout) ? n : (Nout - 1);
        wrow[nt] = Wh + (size_t)nc * ld;
    }

    const int KC = ld / 32;
    for (int kc = 0; kc < KC; kc++) {
#pragma unroll
        for (int ks = 0; ks < 2; ks++) {
            int d0 = kc*32 + ks*16 + c2;
            unsigned ah[4];
            ah[0] = *(const unsigned*)&a1h[d0];
            ah[1] = *(const unsigned*)&a2h[d0];
            ah[2] = *(const unsigned*)&a1h[d0+8];
            ah[3] = *(const unsigned*)&a2h[d0+8];
#pragma unroll
            for (int nt = 0; nt < 8; nt++) {
                unsigned bh0 = *(const unsigned*)&wrow[nt][d0];
                unsigned bh1 = *(const unsigned*)&wrow[nt][d0+8];
                mma16816(acc[nt], ah, bh0, bh1);
            }
        }
    }

    int m1 = row1, m2 = row1 + 8;
#pragma unroll
    for (int nt = 0; nt < 8; nt++) {
        int n = n0 + nt*8 + c2;
#pragma unroll
        for (int j = 0; j < 2; j++) {
            int nn = n + j;
            if (nn >= Nout) continue;
            float v1 = acc[nt][j]   + bias[nn];
            float v2 = acc[nt][2+j] + bias[nn];
            if (mode == 0) {
                out[(size_t)m1*ldo + nn] = v1;
                out[(size_t)m2*ldo + nn] = v2;
            } else if (mode == 1) {
                size_t i1 = (size_t)m1*ldo + nn, i2 = (size_t)m2*ldo + nn;
                out[i1] = v1 + res[i1];
                out[i2] = v2 + res[i2];
            } else if (mode == 2) {
                int b1 = m1 / Nn, t1i = m1 - b1*Nn;
                int b2 = m2 / Nn, t2i = m2 - b2*Nn;
                size_t i1 = ((size_t)b1*Cn + nn)*Nn + t1i;
                size_t i2 = ((size_t)b2*Cn + nn)*Nn + t2i;
                out[i1] = v1 + res[i1];
                out[i2] = v2 + res[i2];
            } else {
                __half* oh = (__half*)out;
                oh[(size_t)m1*ldo + nn] = __float2half_rn(v1);
                oh[(size_t)m2*ldo + nn] = __float2half_rn(v2);
            }
        }
    }
}

// ---------- HMMA kv GEMM with fused l2norm/split epilogue -> kph/vph fp16 ----------
__global__ void __launch_bounds__(128) hgemm_kv(
    const __half* __restrict__ Ah, const __half* __restrict__ Wh,
    const float* __restrict__ bias,
    __half* __restrict__ kph, __half* __restrict__ vph)
{
    const int m0 = blockIdx.y * 64;
    const int n0 = blockIdx.x * 64;
    const int warp = threadIdx.x >> 5;
    const int lane = threadIdx.x & 31;
    const int r  = lane >> 2;
    const int c2 = (lane & 3) * 2;
    const int ld = 128;

    float acc[8][4];
#pragma unroll
    for (int t = 0; t < 8; t++)
#pragma unroll
        for (int i = 0; i < 4; i++) acc[t][i] = 0.f;

    const int row1 = m0 + warp*16 + r;
    const __half* a1h = Ah + (size_t)row1 * ld;
    const __half* a2h = a1h + (size_t)8 * ld;

    const int nr = n0 + (lane >> 2);
    const __half* wrow[8];
#pragma unroll
    for (int nt = 0; nt < 8; nt++)
        wrow[nt] = Wh + (size_t)(nr + nt*8) * ld;

#pragma unroll
    for (int kc = 0; kc < 4; kc++) {
#pragma unroll
        for (int ks = 0; ks < 2; ks++) {
            int d0 = kc*32 + ks*16 + c2;
            unsigned ah[4];
            ah[0] = *(const unsigned*)&a1h[d0];
            ah[1] = *(const unsigned*)&a2h[d0];
            ah[2] = *(const unsigned*)&a1h[d0+8];
            ah[3] = *(const unsigned*)&a2h[d0+8];
#pragma unroll
            for (int nt = 0; nt < 8; nt++) {
                unsigned bh0 = *(const unsigned*)&wrow[nt][d0];
                unsigned bh1 = *(const unsigned*)&wrow[nt][d0+8];
                mma16816(acc[nt], ah, bh0, bh1);
            }
        }
    }

#pragma unroll
    for (int half = 0; half < 2; half++) {
        int m = row1 + half*8;
        int bb = m / Nn, n = m - bb*Nn;
        float vals[16];
#pragma unroll
        for (int nt = 0; nt < 8; nt++)
#pragma unroll
            for (int j = 0; j < 2; j++)
                vals[nt*2+j] = acc[nt][half*2+j] + bias[n0 + nt*8 + c2 + j];
        if (n0 < 128) {
            float se = 0.f, so = 0.f;
#pragma unroll
            for (int i = 0; i < 8; i++) { se += vals[i]*vals[i]; so += vals[8+i]*vals[8+i]; }
            se += __shfl_xor_sync(0xffffffffu, se, 1);
            se += __shfl_xor_sync(0xffffffffu, se, 2);
            so += __shfl_xor_sync(0xffffffffu, so, 1);
            so += __shfl_xor_sync(0xffffffffu, so, 2);
            float ke = 1.0f / fmaxf(sqrtf(se), 1e-12f);
            float ko = 1.0f / fmaxf(sqrtf(so), 1e-12f);
#pragma unroll
            for (int nt = 0; nt < 8; nt++) {
                int col = n0 + nt*8 + c2;
                int head = col >> 5;
                float sc = (nt < 4) ? ke : ko;
                __half2 hv = __floats2half2_rn(vals[nt*2]*sc, vals[nt*2+1]*sc);
                *(__half2*)&kph[((size_t)(bb*NHn + head)*Nn + n)*32 + (col & 31)] = hv;
            }
        } else {
#pragma unroll
            for (int nt = 0; nt < 8; nt++) {
                int col = n0 - 128 + nt*8 + c2;
                int head = col >> 5;
                __half2 hv = __floats2half2_rn(vals[nt*2], vals[nt*2+1]);
                *(__half2*)&vph[((size_t)(bb*NHn + head)*Nn + n)*32 + (col & 31)] = hv;
            }
        }
    }
}

// ---------- pointwise after fused QKVSR GEMM (qs pre-scaled by log2e) ----------
__global__ void pointwise1(const __half* __restrict__ t1h, const float* __restrict__ temp,
                           const float* __restrict__ qe, const float* __restrict__ plnw,
                           const float* __restrict__ plnb,
                           __half* __restrict__ qsh, __half* __restrict__ qnh,
                           __half* __restrict__ klh, __half* __restrict__ vlh,
                           __half* __restrict__ xph)
{
    int t = blockIdx.x * 8 + (threadIdx.x >> 5);
    int lane = threadIdx.x & 31;
    int bb = t / Nn, n = t - bb * Nn;
    int h = lane >> 3;
    int g = bb * NHn + h;
    const __half2* row = (const __half2*)(t1h + (size_t)t * 512);
    unsigned base = ((unsigned)g*Nn + n)*16 + (lane & 7)*2;

    __half2 qa = row[2*lane], qb = row[2*lane + 1];
    float q0 = __half2float(qa.x), q1 = __half2float(qa.y);
    float q2 = __half2float(qb.x), q3 = __half2float(qb.y);
    float ss = q0*q0 + q1*q1 + q2*q2 + q3*q3;
    ss += __shfl_xor_sync(0xffffffffu, ss, 1);
    ss += __shfl_xor_sync(0xffffffffu, ss, 2);
    ss += __shfl_xor_sync(0xffffffffu, ss, 4);
    float inv = 1.0f / fmaxf(sqrtf(ss), 1e-12f);
    float n0 = q0*inv, n1 = q1*inv, n2 = q2*inv, n3 = q3*inv;
    float tv = temp[h];
    float sp = log1pf(__expf(tv)) * LOG2E;
    float4 qe4 = ((const float4*)qe)[h*8 + (lane & 7)];
    ((unsigned*)qnh)[base]   = h2pack(n0, n1);
    ((unsigned*)qnh)[base+1] = h2pack(n2, n3);
    ((unsigned*)qsh)[base]   = h2pack((n0+qe4.x)*sp, (n1+qe4.y)*sp);
    ((unsigned*)qsh)[base+1] = h2pack((n2+qe4.z)*sp, (n3+qe4.w)*sp);

    __half2 ka = row[64 + 2*lane], kb = row[64 + 2*lane + 1];
    float k0 = __half2float(ka.x), k1 = __half2float(ka.y);
    float k2 = __half2float(kb.x), k3 = __half2float(kb.y);
    float ks = k0*k0 + k1*k1 + k2*k2 + k3*k3;
    ks += __shfl_xor_sync(0xffffffffu, ks, 1);
    ks += __shfl_xor_sync(0xffffffffu, ks, 2);
    ks += __shfl_xor_sync(0xffffffffu, ks, 4);
    float ki = 1.0f / fmaxf(sqrtf(ks), 1e-12f);
    ((unsigned*)klh)[base]   = h2pack(k0*ki, k1*ki);
    ((unsigned*)klh)[base+1] = h2pack(k2*ki, k3*ki);

    ((unsigned*)vlh)[base]   = *(const unsigned*)&row[128 + 2*lane];
    ((unsigned*)vlh)[base+1] = *(const unsigned*)&row[128 + 2*lane + 1];

    __half2 sa = row[192 + 2*lane], sb = row[192 + 2*lane + 1];
    float g0 = gelu_exact(__half2float(sa.x)), g1 = gelu_exact(__half2float(sa.y));
    float g2 = gelu_exact(__half2float(sb.x)), g3 = gelu_exact(__half2float(sb.y));
    float sm = g0+g1+g2+g3;
    float sq = g0*g0+g1*g1+g2*g2+g3*g3;
#pragma unroll
    for (int d = 1; d < 32; d <<= 1) {
        sm += __shfl_xor_sync(0xffffffffu, sm, d);
        sq += __shfl_xor_sync(0xffffffffu, sq, d);
    }
    float mu = sm*(1.0f/128.0f);
    float rstd = rsqrtf(sq*(1.0f/128.0f) - mu*mu + 1e-5f);
    int c = lane * 4;
    float o0 = (g0-mu)*rstd*plnw[c]   + plnb[c];
    float o1 = (g1-mu)*rstd*plnw[c+1] + plnb[c+1];
    float o2 = (g2-mu)*rstd*plnw[c+2] + plnb[c+2];
    float o3 = (g3-mu)*rstd*plnw[c+3] + plnb[c+3];
    unsigned* xh = (unsigned*)xph;
    xh[(size_t)t*64 + lane*2]     = h2pack(o0, o1);
    xh[(size_t)t*64 + lane*2 + 1] = h2pack(o2, o3);
}

// ---------- HMMA pooled attention: double-buffered staging + ldmatrix + ex2 ----------
#define BUFB 10240u   // 128*40*2 bytes per buffer
__global__ void __launch_bounds__(256) attn_pool_mma(
    const __half* __restrict__ qsh, const __half* __restrict__ kph,
    const __half* __restrict__ vph,
    const __half* __restrict__ qnh, const __half* __restrict__ klh,
    const __half* __restrict__ vlh, const float* __restrict__ lt,
    const float* __restrict__ lb,
    __half* __restrict__ atth)
{
    __shared__ __half Khi[2][128][40];
    __shared__ __half Vr [2][128][40];   // row-major V; col 32 = valid mask, 33-39 = 0

    const int g  = blockIdx.y;
    const int tid = threadIdx.x;
    const int warp = tid >> 5;
    const int lane = tid & 31;
    const int r  = lane >> 2;
    const int c2 = (lane & 3) * 2;
    const int qbase = blockIdx.x * 128 + (warp >> 2) * 64 + (warp & 3) * 16 + r;
    const int qrow_l = (qbase < Nn) ? qbase : (Nn - 1);

    const unsigned sK = smem_u32(Khi);
    const unsigned sV = smem_u32(Vr);
    const int l7 = lane & 7;
    const unsigned qk_base = sK + (unsigned)((l7 + ((lane >> 4) << 3)) * 80 + ((lane >> 3) & 1) * 16);
    const unsigned ev_base = sV + (unsigned)((l7 + ((lane >> 3) & 1) * 8) * 80 + ((lane >> 4) & 1) * 16);
    const unsigned evt_base = sV + (unsigned)((l7 + ((lane >> 3) & 1) * 8) * 80 + 64);

    const int row = tid & 127;
    const int hp  = tid >> 7;

    unsigned qhi[2][4];
    {
        const __half* q0p = qsh + ((size_t)g*Nn + qrow_l)*32;
        int q8c = (qbase + 8 < Nn) ? (qbase + 8) : (Nn - 1);
        const __half* q8p = qsh + ((size_t)g*Nn + q8c)*32;
#pragma unroll
        for (int ks = 0; ks < 2; ks++) {
            int d0 = ks*16 + c2;
            qhi[ks][0] = *(const unsigned*)&q0p[d0];
            qhi[ks][1] = *(const unsigned*)&q8p[d0];
            qhi[ks][2] = *(const unsigned*)&q0p[d0+8];
            qhi[ks][3] = *(const unsigned*)&q8p[d0+8];
        }
    }

    float uf[5][4];
#pragma unroll
    for (int t = 0; t < 5; t++)
#pragma unroll
        for (int i = 0; i < 4; i++) uf[t][i] = 0.f;

    const int NCH = 25;
    // stage chunk 0 into buffer 0
    {
        int kvr = row;
        bool ok = kvr < Nn;
        size_t rb = ((size_t)g*Nn + kvr)*32;
        const uint4* krh = (const uint4*)(kph + rb);
        const uint4* vr4 = (const uint4*)(vph + rb);
#pragma unroll
        for (int j = 0; j < 2; j++) {
            *(uint4*)&Khi[0][row][(hp*2 + j)*8] = krh[hp*2 + j];
            *(uint4*)&Vr [0][row][(hp*2 + j)*8] = vr4[hp*2 + j];
        }
        if (hp) *(uint4*)&Vr[0][row][32] = make_uint4(0x00003C00u, 0u, 0u, 0u);
        (void)ok;
    }
    __syncthreads();

    for (int ch = 0; ch < NCH; ch++) {
        const int m0 = ch * 128;
        const int cur = ch & 1;
        const unsigned boff = cur * BUFB;

        // prefetch next chunk to registers
        uint4 pk0, pk1, pv0, pv1;
        bool pok = false;
        if (ch + 1 < NCH) {
            int kvr = m0 + 128 + row;
            pok = kvr < Nn;
            size_t rb = ((size_t)g*Nn + (pok ? kvr : 0))*32;
            const uint4* krh = (const uint4*)(kph + rb);
            const uint4* vr4 = (const uint4*)(vph + rb);
            uint4 z4 = make_uint4(0,0,0,0);
            pk0 = pok ? krh[hp*2]     : z4;
            pk1 = pok ? krh[hp*2 + 1] : z4;
            pv0 = pok ? vr4[hp*2]     : z4;
            pv1 = pok ? vr4[hp*2 + 1] : z4;
        }

        const int kkmax = (m0 + 128 <= Nn) ? 8 : 4;
        for (int kk = 0; kk < kkmax; kk++) {
            const unsigned qka = qk_base + boff + kk*1280;
            float s0[4] = {0.f,0.f,0.f,0.f};
            float s1[4] = {0.f,0.f,0.f,0.f};
#pragma unroll
            for (int ks = 0; ks < 2; ks++) {
                unsigned b00, b01, b10, b11;
                LDSM_X4(b00, b01, b10, b11, qka + ks*32);
                mma16816(s0, qhi[ks], b00, b01);
                mma16816(s1, qhi[ks], b10, b11);
            }
            unsigned ea[4];
            ea[0] = ex2_h2(h2pack(s0[0], s0[1]));
            ea[1] = ex2_h2(h2pack(s0[2], s0[3]));
            ea[2] = ex2_h2(h2pack(s1[0], s1[1]));
            ea[3] = ex2_h2(h2pack(s1[2], s1[3]));

            const unsigned eva = ev_base + boff + kk*1280;
#pragma unroll
            for (int ntp = 0; ntp < 2; ntp++) {
                unsigned v0, v1, v2, v3;
                LDSM_X4T(v0, v1, v2, v3, eva + ntp*32);
                mma16816(uf[2*ntp],     ea, v0, v1);
                mma16816(uf[2*ntp + 1], ea, v2, v3);
            }
            unsigned t0, t1;
            LDSM_X2T(t0, t1, evt_base + boff + kk*1280);
            mma16816(uf[4], ea, t0, t1);
        }

        if (ch + 1 < NCH) {
            int nb = 1 - cur;
            *(uint4*)&Khi[nb][row][hp*16]     = pk0;
            *(uint4*)&Khi[nb][row][hp*16 + 8] = pk1;
            *(uint4*)&Vr [nb][row][hp*16]     = pv0;
            *(uint4*)&Vr [nb][row][hp*16 + 8] = pv1;
            if (hp) *(uint4*)&Vr[nb][row][32] = make_uint4(pok ? 0x00003C00u : 0u, 0u, 0u, 0u);
        }
        __syncthreads();
    }

    // Z sits at col 32 (uf[4], tile col 0) held by quad-base lane
    float z0 = __shfl_sync(0xffffffffu, uf[4][0], lane & 28);
    float z1 = __shfl_sync(0xffffffffu, uf[4][2], lane & 28);

    const int b = g >> 2, h = g & 3;
#pragma unroll
    for (int half = 0; half < 2; half++) {
        int n = qbase + half*8;
        bool nok = n < Nn;
        int nc = nok ? n : (Nn - 1);
        float Zpool = half ? z1 : z0;
        int hh = nc / Hs, ww = nc - hh*Hs;
        const __half* qp  = qsh + ((size_t)g*Nn + nc)*32;
        const __half* qnp = qnh + ((size_t)g*Nn + nc)*32;
        float qsv[8], qnv[8];
#pragma unroll
        for (int nt = 0; nt < 4; nt++) {
            int c = nt*8 + c2;
            __half2 a = *(const __half2*)&qp[c];
            __half2 bq = *(const __half2*)&qnp[c];
            qsv[nt*2]   = __half2float(a.x);  qsv[nt*2+1] = __half2float(a.y);
            qnv[nt*2]   = __half2float(bq.x); qnv[nt*2+1] = __half2float(bq.y);
        }
        float resv[8], res2v[8];
#pragma unroll
        for (int i = 0; i < 8; i++) { resv[i] = 0.f; res2v[i] = 0.f; }
        float zl = 0.f;
#pragma unroll
        for (int k = 0; k < 9; k++) {
            int h2 = hh + k/3 - 1, w2 = ww + (k%3) - 1;
            bool ok = (h2 >= 0 && h2 < Hs && w2 >= 0 && w2 < Hs);
            size_t bi = ((size_t)g*Nn + (ok ? (h2*Hs + w2) : 0))*32;
            float klv[8], vlv[8];
            float lg = 0.f, wl = 0.f;
#pragma unroll
            for (int nt = 0; nt < 4; nt++) {
                int c = nt*8 + c2;
                __half2 kk2 = ok ? *(const __half2*)&klh[bi + c] : __half2(__float2half(0.f), __float2half(0.f));
                __half2 vv2 = ok ? *(const __half2*)&vlh[bi + c] : __half2(__float2half(0.f), __float2half(0.f));
                int idx = nt*2;
                klv[idx]   = __half2float(kk2.x); klv[idx+1] = __half2float(kk2.y);
                vlv[idx]   = __half2float(vv2.x); vlv[idx+1] = __half2float(vv2.y);
                lg += qsv[idx]*klv[idx] + qsv[idx+1]*klv[idx+1];
                wl += qnv[idx]*lt[(h*32 + c)*9 + k] + qnv[idx+1]*lt[(h*32 + c + 1)*9 + k];
            }
            lg += __shfl_xor_sync(0xffffffffu, lg, 1);
            lg += __shfl_xor_sync(0xffffffffu, lg, 2);
            wl += __shfl_xor_sync(0xffffffffu, wl, 1);
            wl += __shfl_xor_sync(0xffffffffu, wl, 2);
            float e = exp2f(lg);
            zl += e;
            float w2l = wl + lb[h*9 + k];
#pragma unroll
            for (int i = 0; i < 8; i++) {
                resv[i]  += e   * vlv[i];
                res2v[i] += w2l * vlv[i];
            }
        }
        float Zf = Zpool + zl;
        float rZ = 1.0f / Zf;
        if (nok) {
#pragma unroll
            for (int nt = 0; nt < 4; nt++)
#pragma unroll
                for (int j = 0; j < 2; j++) {
                    int c = nt*8 + c2 + j;
                    int idx = nt*2 + j;
                    float o = (uf[nt][half*2 + j] + resv[idx]) * rZ + res2v[idx];
                    size_t oi = ((size_t)(b*Nn + n))*128 + h*32 + c;
                    atth[oi] = __float2half_rn(o);
                }
        }
    }
}

// ---------- depthwise 3x3 + gelu * v: 2 adjacent tokens per thread ----------
__global__ void __launch_bounds__(LDF) dwconv_kernel(
    const __half* __restrict__ f1, const float* __restrict__ dww,
    const float* __restrict__ dwb, __half* __restrict__ gbh)
{
    int t0 = blockIdx.x * 2;
    int c = threadIdx.x;
    size_t o0 = (size_t)t0*LDF + c, o1 = o0 + LDF;
    if (c >= HFn) {
        gbh[o0] = __float2half(0.f);
        gbh[o1] = __float2half(0.f);
        return;
    }
    int b = t0 / Nn, n = t0 - b*Nn;
    int hh = n / Hs, ww = n - hh*Hs;
    float w[9];
#pragma unroll
    for (int k = 0; k < 9; k++) w[k] = dww[c*9 + k];
    float acc0 = dwb[c], acc1 = acc0;
#pragma unroll
    for (int dr = -1; dr <= 1; dr++) {
        int h2 = hh + dr;
        if (h2 < 0 || h2 >= Hs) continue;
#pragma unroll
        for (int dc = -1; dc <= 2; dc++) {
            int w2 = ww + dc;
            if (w2 < 0 || w2 >= Hs) continue;
            float v = __half2float(f1[((size_t)(b*Nn + h2*Hs + w2))*682 + c]);
            if (dc <= 1) acc0 += v * w[(dr+1)*3 + dc + 1];
            if (dc >= 0) acc1 += v * w[(dr+1)*3 + dc];
        }
    }
    float v0 = __half2float(f1[(size_t)t0*682 + 341 + c]);
    float v1 = __half2float(f1[(size_t)(t0+1)*682 + 341 + c]);
    gbh[o0] = __float2half_rn(gelu_exact(acc0) * v0);
    gbh[o1] = __float2half_rn(gelu_exact(acc1) * v1);
}

extern "C" void kernel_launch(void* const* d_in, const int* in_sizes, int n_in,
                              void* d_out, int out_size)
{
    const float* x      = (const float*)d_in[0];
    const float* n1w    = (const float*)d_in[1];
    const float* n1b    = (const float*)d_in[2];
    const float* q_w    = (const float*)d_in[3];
    const float* q_b    = (const float*)d_in[4];
    const float* kv_w   = (const float*)d_in[5];
    const float* kv_b   = (const float*)d_in[6];
    const float* temp   = (const float*)d_in[7];
    const float* qe     = (const float*)d_in[8];
    const float* lt     = (const float*)d_in[9];
    const float* lb     = (const float*)d_in[10];
    const float* sr_w   = (const float*)d_in[11];
    const float* sr_b   = (const float*)d_in[12];
    const float* plnw   = (const float*)d_in[13];
    const float* plnb   = (const float*)d_in[14];
    const float* proj_w = (const float*)d_in[15];
    const float* proj_b = (const float*)d_in[16];
    const float* n2w    = (const float*)d_in[17];
    const float* n2b    = (const float*)d_in[18];
    const float* fc1_w  = (const float*)d_in[19];
    const float* fc1_b  = (const float*)d_in[20];
    const float* dw_w   = (const float*)d_in[21];
    const float* dw_b   = (const float*)d_in[22];
    const float* fc2_w  = (const float*)d_in[23];
    const float* fc2_b  = (const float*)d_in[24];
    float* out = (float*)d_out;

    float *x2b, *b512;
    __half *t1h, *qshb, *qnhb, *klhb, *vlhb, *f1hb, *yh, *xph, *atth, *y2h, *kph, *vphh, *gbh, *wh;
    cudaGetSymbolAddress((void**)&x2b,  g_x2);
    cudaGetSymbolAddress((void**)&b512, g_b512);
    cudaGetSymbolAddress((void**)&t1h,  g_t1h);
    cudaGetSymbolAddress((void**)&qshb, g_qsh);
    cudaGetSymbolAddress((void**)&qnhb, g_qnh);
    cudaGetSymbolAddress((void**)&klhb, g_klh);
    cudaGetSymbolAddress((void**)&vlhb, g_vlh);
    cudaGetSymbolAddress((void**)&f1hb, g_f1h);
    cudaGetSymbolAddress((void**)&yh,   g_yh);
    cudaGetSymbolAddress((void**)&xph,  g_xph);
    cudaGetSymbolAddress((void**)&atth, g_atth);
    cudaGetSymbolAddress((void**)&y2h,  g_y2h);
    cudaGetSymbolAddress((void**)&kph,  g_kph);
    cudaGetSymbolAddress((void**)&vphh, g_vph);
    cudaGetSymbolAddress((void**)&gbh,  g_gbh);
    cudaGetSymbolAddress((void**)&wh,   g_wh);

    cvt_all<<<840, 256>>>(q_w, kv_w, sr_w, proj_w, fc1_w, fc2_w, q_b, kv_b, sr_b, wh, b512);

    ln_kernel<<<TOK/8, 256>>>(x, n1w, n1b, yh);
    hgemm2<<<dim3(8,98), 128>>>(yh, wh+OQ, 128, b512, (float*)t1h, 512, 512, 3, nullptr);
    pointwise1<<<TOK/8, 256>>>(t1h, temp, qe, plnw, plnb, qshb, qnhb, klhb, vlhb, xph);
    hgemm_kv<<<dim3(4,98), 128>>>(xph, wh+OKV, kv_b, kph, vphh);
    attn_pool_mma<<<dim3(25,8), 256>>>(qshb, kph, vphh, qnhb, klhb, vlhb, lt, lb, atth);
    hgemm2<<<dim3(2,98), 128>>>(atth, wh+OPJ, 128, proj_b, x2b, 128, 128, 1, x);
    ln_kernel<<<TOK/8, 256>>>(x2b, n2w, n2b, y2h);
    hgemm2<<<dim3(11,98), 128>>>(y2h, wh+OF1, 128, fc1_b, (float*)f1hb, 682, 682, 3, nullptr);
    dwconv_kernel<<<TOK/2, LDF>>>(f1hb, dw_w, dw_b, gbh);
    hgemm2<<<dim3(2,98), 128>>>(gbh, wh+OF2, LDF, fc2_b, out, 128, 128, 2, x2b);
}